// round 12
// baseline (speedup 1.0000x reference)
#include <cuda_runtime.h>
#include <cuda_fp16.h>
#include <cstdint>
#include <math.h>

// Problem constants:
//  x: [16, 512, 64, 64] fp32 == [64 batches][128 ch][4096 px] contiguous
#define NB     64
#define CI     128
#define NPIX   4096
#define KSPLIT 8                 // gram K-split CTAs per batch (K=512 each)
#define GPR    12                // gram pair stride (8 pairs + 4)  [48B, ldsm-cf]
#define APR    68                // packed pair stride (64 pairs + 4) [272B, ldsm-cf]
#define F32S   132               // chain fp32 scratch stride

// ---------------- fp16 helpers ----------------
__device__ __forceinline__ void split2(float a, float b, unsigned& hu, unsigned& lu) {
    __half2 h2 = __float22half2_rn(make_float2(a, b));
    float2 hf = __half22float2(h2);
    __half2 l2 = __float22half2_rn(make_float2(a - hf.x, b - hf.y));
    hu = *(unsigned*)&h2;
    lu = *(unsigned*)&l2;
}
__device__ __forceinline__ void split2s2(float a, float b, unsigned& hu, unsigned& lu) {
    __half2 h2 = __float22half2_rn(make_float2(a, b));
    float2 hf = __half22float2(h2);
    __half2 l2 = __float22half2_rn(make_float2((a - hf.x) * 2.0f, (b - hf.y) * 2.0f));
    hu = *(unsigned*)&h2;
    lu = *(unsigned*)&l2;
}

// D += A(16x16,row,f16) * B(16x8,col,f16)  fp32-accum
__device__ __forceinline__ void mmah(float* d, const unsigned* a, const unsigned* b) {
    asm volatile(
        "mma.sync.aligned.m16n8k16.row.col.f32.f16.f16.f32 "
        "{%0,%1,%2,%3}, {%4,%5,%6,%7}, {%8,%9}, {%0,%1,%2,%3};"
        : "+f"(d[0]), "+f"(d[1]), "+f"(d[2]), "+f"(d[3])
        : "r"(a[0]), "r"(a[1]), "r"(a[2]), "r"(a[3]), "r"(b[0]), "r"(b[1]));
}

__device__ __forceinline__ uint32_t s2u(const void* p) {
    return (uint32_t)__cvta_generic_to_shared(p);
}
#define LDSM_X4(r, addr) \
    asm volatile("ldmatrix.sync.aligned.m8n8.x4.shared.b16 {%0,%1,%2,%3}, [%4];" \
        : "=r"((r)[0]), "=r"((r)[1]), "=r"((r)[2]), "=r"((r)[3]) : "r"(addr))
#define LDSM_X4T(r, addr) \
    asm volatile("ldmatrix.sync.aligned.m8n8.x4.trans.shared.b16 {%0,%1,%2,%3}, [%4];" \
        : "=r"((r)[0]), "=r"((r)[1]), "=r"((r)[2]), "=r"((r)[3]) : "r"(addr))

// ---------------- scratch ----------------
__device__ float    g_Gpart[NB * KSPLIT * CI * CI]; // partial E (G = (E+E^T)/2)
__device__ float    g_spart[NB * KSPLIT * CI];      // partial row sums
__device__ unsigned g_Ah2[NB * CI * 64];            // A'' fp16-hi, half2 pairs
__device__ unsigned g_Al2[NB * CI * 64];            // A'' fp16-lo, half2 pairs
__device__ float    g_bvec[NB * CI];                // folded bias b'

// =====================================================================
// Kernel 1 (round-11 proven, 68.6us): partial E = H H^T + H (2L)^T.
// =====================================================================
__global__ void __launch_bounds__(256, 2)
gram_kernel(const float* __restrict__ X)
{
    __shared__ unsigned sH[2][128 * GPR];
    __shared__ unsigned sL[2][128 * GPR];
    __shared__ float sred[256];

    const int t = threadIdx.x;
    const int lane = t & 31, w = t >> 5;
    const int wr = (w >> 2) * 64, wc = (w & 3) * 32;
    const int qr = lane >> 2, qc = lane & 3;
    const int kc = blockIdx.x, bb = blockIdx.y;

    const float* Xb = X + (size_t)bb * CI * NPIX + (size_t)kc * 512;
    const int lrow = t >> 1, lp4 = (t & 1) * 4;
    const int sbase = lrow * GPR + lp4;
    const float* Xr = Xb + (size_t)lrow * NPIX + lp4 * 2;

    const uint32_t aH[2] = {s2u(sH[0]), s2u(sH[1])};
    const uint32_t aL[2] = {s2u(sL[0]), s2u(sL[1])};

    uint32_t aoffA[4], boffB[2];
#pragma unroll
    for (int m = 0; m < 4; m++)
        aoffA[m] = (uint32_t)((wr + m * 16 + (lane & 15)) * GPR) * 4u
                 + (uint32_t)((lane >> 4) & 1) * 16u;
#pragma unroll
    for (int j = 0; j < 2; j++)
        boffB[j] = (uint32_t)((wc + j * 16 + (lane & 7) + ((lane >> 4) & 1) * 8) * GPR) * 4u
                 + (uint32_t)((lane >> 3) & 1) * 16u;

    float acc[4][4][4];
#pragma unroll
    for (int m = 0; m < 4; m++)
#pragma unroll
        for (int n = 0; n < 4; n++)
#pragma unroll
            for (int r = 0; r < 4; r++) acc[m][n][r] = 0.f;
    float mysum = 0.f;

    {
        float4 v0 = *(const float4*)(Xr);
        float4 v1 = *(const float4*)(Xr + 4);
        unsigned hu[4], lu[4];
        split2s2(v0.x, v0.y, hu[0], lu[0]);
        split2s2(v0.z, v0.w, hu[1], lu[1]);
        split2s2(v1.x, v1.y, hu[2], lu[2]);
        split2s2(v1.z, v1.w, hu[3], lu[3]);
        mysum += v0.x + v0.y + v0.z + v0.w + v1.x + v1.y + v1.z + v1.w;
        *(uint4*)&sH[0][sbase] = make_uint4(hu[0], hu[1], hu[2], hu[3]);
        *(uint4*)&sL[0][sbase] = make_uint4(lu[0], lu[1], lu[2], lu[3]);
    }
    __syncthreads();

    for (int ch = 0; ch < 32; ch++) {
        const int b = ch & 1;
        float4 n0, n1;
        if (ch < 31) {
            n0 = *(const float4*)(Xr + (ch + 1) * 16);
            n1 = *(const float4*)(Xr + (ch + 1) * 16 + 4);
        }

        unsigned Af[4][4];
#pragma unroll
        for (int m = 0; m < 4; m++) LDSM_X4(Af[m], aH[b] + aoffA[m]);
#pragma unroll
        for (int j = 0; j < 2; j++) {
            unsigned BH[4], BL[4];
            LDSM_X4(BH, aH[b] + boffB[j]);
            LDSM_X4(BL, aL[b] + boffB[j]);
            unsigned B0h[2] = {BH[0], BH[1]}, B1h[2] = {BH[2], BH[3]};
            unsigned B0l[2] = {BL[0], BL[1]}, B1l[2] = {BL[2], BL[3]};
#pragma unroll
            for (int m = 0; m < 4; m++) {
                mmah(acc[m][2 * j],     Af[m], B0h);
                mmah(acc[m][2 * j],     Af[m], B0l);
                mmah(acc[m][2 * j + 1], Af[m], B1h);
                mmah(acc[m][2 * j + 1], Af[m], B1l);
            }
        }

        if (ch < 31) {
            unsigned hu[4], lu[4];
            split2s2(n0.x, n0.y, hu[0], lu[0]);
            split2s2(n0.z, n0.w, hu[1], lu[1]);
            split2s2(n1.x, n1.y, hu[2], lu[2]);
            split2s2(n1.z, n1.w, hu[3], lu[3]);
            mysum += n0.x + n0.y + n0.z + n0.w + n1.x + n1.y + n1.z + n1.w;
            *(uint4*)&sH[b ^ 1][sbase] = make_uint4(hu[0], hu[1], hu[2], hu[3]);
            *(uint4*)&sL[b ^ 1][sbase] = make_uint4(lu[0], lu[1], lu[2], lu[3]);
        }
        __syncthreads();
    }

    sred[t] = mysum;
    __syncthreads();
    if (t < 128)
        g_spart[(bb * KSPLIT + kc) * CI + t] = sred[2 * t] + sred[2 * t + 1];

    float* P = g_Gpart + ((size_t)(bb * KSPLIT + kc)) * CI * CI;
#pragma unroll
    for (int m = 0; m < 4; m++) {
        const int r0 = wr + m * 16 + qr;
#pragma unroll
        for (int n = 0; n < 4; n++) {
            const int c0 = wc + n * 8 + qc * 2;
            *(float2*)(P + (size_t)r0 * CI + c0)       = make_float2(acc[m][n][0], acc[m][n][1]);
            *(float2*)(P + (size_t)(r0 + 8) * CI + c0) = make_float2(acc[m][n][2], acc[m][n][3]);
        }
    }
}

// =====================================================================
// Kernel 2: chain, tensorized (round-10 proven, unchanged).
// =====================================================================
#define CH_PK   (128 * APR * 4)
#define CH_OF32 (4 * CH_PK)
#define CH_SMEM (CH_OF32 + 128 * F32S * 4)

__device__ __forceinline__ void mgh3(const unsigned* __restrict__ Ah,
                                     const unsigned* __restrict__ Al,
                                     const unsigned* __restrict__ Bh,
                                     const unsigned* __restrict__ Bl,
                                     float* __restrict__ O, int t)
{
    const int lane = t & 31, w = t >> 5;
    const int wr = (w >> 2) * 64, wc = (w & 3) * 32;
    const int qr = lane >> 2, qc = lane & 3;
    float acc[4][4][4];
#pragma unroll
    for (int m = 0; m < 4; m++)
#pragma unroll
        for (int n = 0; n < 4; n++)
#pragma unroll
            for (int r = 0; r < 4; r++) acc[m][n][r] = 0.f;

#pragma unroll
    for (int s = 0; s < 8; s++) {
        const int kp = s * 8;
        unsigned Afh[4][4], Afl[4][4];
#pragma unroll
        for (int m = 0; m < 4; m++) {
            const int ar = wr + m * 16 + qr;
            Afh[m][0] = Ah[ar * APR + kp + qc];
            Afh[m][1] = Ah[(ar + 8) * APR + kp + qc];
            Afh[m][2] = Ah[ar * APR + kp + qc + 4];
            Afh[m][3] = Ah[(ar + 8) * APR + kp + qc + 4];
            Afl[m][0] = Al[ar * APR + kp + qc];
            Afl[m][1] = Al[(ar + 8) * APR + kp + qc];
            Afl[m][2] = Al[ar * APR + kp + qc + 4];
            Afl[m][3] = Al[(ar + 8) * APR + kp + qc + 4];
        }
#pragma unroll
        for (int n = 0; n < 4; n++) {
            const int br = wc + n * 8 + qr;
            unsigned Bfh[2] = {Bh[br * APR + kp + qc], Bh[br * APR + kp + qc + 4]};
            unsigned Bfl[2] = {Bl[br * APR + kp + qc], Bl[br * APR + kp + qc + 4]};
#pragma unroll
            for (int m = 0; m < 4; m++) {
                mmah(acc[m][n], Afh[m], Bfh);
                mmah(acc[m][n], Afh[m], Bfl);
                mmah(acc[m][n], Afl[m], Bfh);
            }
        }
    }
#pragma unroll
    for (int m = 0; m < 4; m++) {
        const int r0 = wr + m * 16 + qr;
#pragma unroll
        for (int n = 0; n < 4; n++) {
            const int c0 = wc + n * 8 + qc * 2;
            *(float2*)&O[r0 * F32S + c0]       = make_float2(acc[m][n][0], acc[m][n][1]);
            *(float2*)&O[(r0 + 8) * F32S + c0] = make_float2(acc[m][n][2], acc[m][n][3]);
        }
    }
}

__device__ __forceinline__ void mgh3_final(const unsigned* __restrict__ Ah,
                                           const unsigned* __restrict__ Al,
                                           const unsigned* __restrict__ Bh,
                                           const unsigned* __restrict__ Bl,
                                           unsigned* __restrict__ gAh,
                                           unsigned* __restrict__ gAl,
                                           const float* __restrict__ scale, int t)
{
    const int lane = t & 31, w = t >> 5;
    const int wr = (w >> 2) * 64, wc = (w & 3) * 32;
    const int qr = lane >> 2, qc = lane & 3;
    float acc[4][4][4];
#pragma unroll
    for (int m = 0; m < 4; m++)
#pragma unroll
        for (int n = 0; n < 4; n++)
#pragma unroll
            for (int r = 0; r < 4; r++) acc[m][n][r] = 0.f;

#pragma unroll
    for (int s = 0; s < 8; s++) {
        const int kp = s * 8;
        unsigned Afh[4][4], Afl[4][4];
#pragma unroll
        for (int m = 0; m < 4; m++) {
            const int ar = wr + m * 16 + qr;
            Afh[m][0] = Ah[ar * APR + kp + qc];
            Afh[m][1] = Ah[(ar + 8) * APR + kp + qc];
            Afh[m][2] = Ah[ar * APR + kp + qc + 4];
            Afh[m][3] = Ah[(ar + 8) * APR + kp + qc + 4];
            Afl[m][0] = Al[ar * APR + kp + qc];
            Afl[m][1] = Al[(ar + 8) * APR + kp + qc];
            Afl[m][2] = Al[ar * APR + kp + qc + 4];
            Afl[m][3] = Al[(ar + 8) * APR + kp + qc + 4];
        }
#pragma unroll
        for (int n = 0; n < 4; n++) {
            const int br = wc + n * 8 + qr;
            unsigned Bfh[2] = {Bh[br * APR + kp + qc], Bh[br * APR + kp + qc + 4]};
            unsigned Bfl[2] = {Bl[br * APR + kp + qc], Bl[br * APR + kp + qc + 4]};
#pragma unroll
            for (int m = 0; m < 4; m++) {
                mmah(acc[m][n], Afh[m], Bfh);
                mmah(acc[m][n], Afh[m], Bfl);
                mmah(acc[m][n], Afl[m], Bfh);
            }
        }
    }
#pragma unroll
    for (int m = 0; m < 4; m++) {
        const int r0 = wr + m * 16 + qr;
        const float s0 = scale[r0], s1 = scale[r0 + 8];
#pragma unroll
        for (int n = 0; n < 4; n++) {
            const int c0 = wc + n * 8 + qc * 2;
            float v0 = s0 * acc[m][n][0] + ((r0 == c0) ? 1.f : 0.f);
            float v1 = s0 * acc[m][n][1] + ((r0 == c0 + 1) ? 1.f : 0.f);
            float v2 = s1 * acc[m][n][2] + ((r0 + 8 == c0) ? 1.f : 0.f);
            float v3 = s1 * acc[m][n][3] + ((r0 + 8 == c0 + 1) ? 1.f : 0.f);
            unsigned hu, lu;
            split2(v0, v1, hu, lu);
            gAh[r0 * 64 + c0 / 2] = hu;
            gAl[r0 * 64 + c0 / 2] = lu;
            split2(v2, v3, hu, lu);
            gAh[(r0 + 8) * 64 + c0 / 2] = hu;
            gAl[(r0 + 8) * 64 + c0 / 2] = lu;
        }
    }
}

__device__ __forceinline__ void stage_pack_gmem(const float* __restrict__ src,
                                                unsigned* __restrict__ Ph,
                                                unsigned* __restrict__ Pl, int t)
{
    const int row = t >> 1, seg = (t & 1) * 64;
    const int base = row * APR + seg / 2;
    const float4* s4 = (const float4*)(src + row * CI + seg);
#pragma unroll
    for (int j = 0; j < 16; j++) {
        float4 v = s4[j];
        unsigned h0, l0, h1, l1;
        split2(v.x, v.y, h0, l0);
        split2(v.z, v.w, h1, l1);
        *(uint2*)&Ph[base + 2 * j] = make_uint2(h0, h1);
        *(uint2*)&Pl[base + 2 * j] = make_uint2(l0, l1);
    }
}

__device__ __forceinline__ void pack_from_smem(const float* __restrict__ F,
                                               unsigned* __restrict__ Ph,
                                               unsigned* __restrict__ Pl, int t)
{
    const int row = t >> 1, seg = (t & 1) * 64;
    const int base = row * APR + seg / 2;
    const float* fr = F + row * F32S + seg;
#pragma unroll
    for (int j = 0; j < 32; j++) {
        float2 v = *(const float2*)(fr + 2 * j);
        unsigned h, l;
        split2(v.x, v.y, h, l);
        Ph[base + j] = h;
        Pl[base + j] = l;
    }
}

__device__ __forceinline__ float dot_packed(const unsigned* __restrict__ Ph,
                                            const unsigned* __restrict__ Pl,
                                            int row, const float* __restrict__ s)
{
    float acc = 0.f;
#pragma unroll 8
    for (int p = 0; p < 64; p++) {
        float2 hf = __half22float2(*(const __half2*)&Ph[row * APR + p]);
        float2 lf = __half22float2(*(const __half2*)&Pl[row * APR + p]);
        acc += (hf.x + lf.x) * s[2 * p] + (hf.y + lf.y) * s[2 * p + 1];
    }
    return acc;
}

__global__ void __launch_bounds__(256)
chain_kernel(const float* __restrict__ theta_w, const float* __restrict__ theta_b,
             const float* __restrict__ phi_w,   const float* __restrict__ phi_b,
             const float* __restrict__ g_w,     const float* __restrict__ g_b,
             const float* __restrict__ W_w,     const float* __restrict__ W_b,
             const float* __restrict__ bn_gamma, const float* __restrict__ bn_beta,
             const float* __restrict__ bn_mean,  const float* __restrict__ bn_var)
{
    extern __shared__ char csm[];
    unsigned* P0h = (unsigned*)(csm);
    unsigned* P0l = (unsigned*)(csm + CH_PK);
    unsigned* P1h = (unsigned*)(csm + 2 * CH_PK);
    unsigned* P1l = (unsigned*)(csm + 3 * CH_PK);
    float*    F32 = (float*)(csm + CH_OF32);

    __shared__ float sv_s[CI], sv_u[CI], sv_q[CI], sv_tb[CI],
                     sv_gb[CI], sv_c[CI], sv_scale[CI];

    const int t  = threadIdx.x;
    const int bb = blockIdx.x;

    const float* Gp = g_Gpart + (size_t)bb * KSPLIT * CI * CI;
    for (int idx = t; idx < CI * CI; idx += 256) {
        float v = 0.f;
#pragma unroll
        for (int ks = 0; ks < KSPLIT; ks++) v += Gp[ks * CI * CI + idx];
        F32[(idx >> 7) * F32S + (idx & 127)] = v;
    }
    if (t < CI) {
        float v = 0.f;
#pragma unroll
        for (int ks = 0; ks < KSPLIT; ks++) v += g_spart[(bb * KSPLIT + ks) * CI + t];
        sv_s[t]  = v;
        sv_tb[t] = theta_b[t];
        sv_gb[t] = g_b[t];
        sv_scale[t] = bn_gamma[t] * rsqrtf(bn_var[t] + 1e-5f);
    }
    stage_pack_gmem(theta_w, P1h, P1l, t);
    __syncthreads();

    for (int i = t; i < 8256; i += 256) {
        int r = (int)((sqrtf(8.0f * (float)i + 1.0f) - 1.0f) * 0.5f);
        if ((r + 1) * (r + 2) / 2 <= i) r++;
        if (r * (r + 1) / 2 > i) r--;
        int c = i - r * (r + 1) / 2;
        float a = F32[r * F32S + c], b = F32[c * F32S + r];
        float g = 0.5f * (a + b);
        F32[r * F32S + c] = g;
        F32[c * F32S + r] = g;
    }
    if (t < CI)
        sv_q[t] = dot_packed(P1h, P1l, t, sv_s) + 4096.0f * sv_tb[t];
    __syncthreads();

    pack_from_smem(F32, P0h, P0l, t);
    __syncthreads();

    mgh3(P1h, P1l, P0h, P0l, F32, t);
    __syncthreads();

    pack_from_smem(F32, P0h, P0l, t);
    stage_pack_gmem(phi_w, P1h, P1l, t);
    __syncthreads();
    if (t < CI)
        sv_u[t] = dot_packed(P1h, P1l, t, sv_s);
    __syncthreads();

    mgh3(P1h, P1l, P0h, P0l, F32, t);
    __syncthreads();

    if (t < CI) {
        const float w1 = sv_u[t];
        const float w2 = phi_b[t];
        float* rowp = F32 + t * F32S;
        float mx = -1e30f;
#pragma unroll 8
        for (int d = 0; d < 128; d++) {
            float v = rowp[d] + w1 * sv_tb[d] + w2 * sv_q[d];
            rowp[d] = v;
            mx = fmaxf(mx, v);
        }
        float ssum = 0.f;
#pragma unroll 8
        for (int d = 0; d < 128; d++) {
            float ev = expf(rowp[d] - mx);
            rowp[d] = ev;
            ssum += ev;
        }
        const float inv = 1.0f / ssum;
        float cacc = 0.f;
#pragma unroll
        for (int p = 0; p < 64; p++) {
            float f0 = rowp[2 * p] * inv;
            float f1 = rowp[2 * p + 1] * inv;
            cacc += f0 * sv_gb[2 * p] + f1 * sv_gb[2 * p + 1];
            unsigned h, l;
            split2(f0, f1, h, l);
            P1h[t * APR + p] = h;
            P1l[t * APR + p] = l;
        }
        sv_c[t] = cacc;
    }
    __syncthreads();

    for (int idx = t; idx < CI * CI; idx += 256)
        F32[(idx >> 7) * F32S + (idx & 127)] = g_w[idx];
    __syncthreads();
    {
        const int k = t >> 1, d0 = (t & 1) * 64;
        const int base = k * APR + d0 / 2;
#pragma unroll
        for (int p = 0; p < 32; p++) {
            const int d = d0 + 2 * p;
            unsigned h, l;
            split2(F32[d * F32S + k], F32[(d + 1) * F32S + k], h, l);
            P0h[base + p] = h;
            P0l[base + p] = l;
        }
    }
    __syncthreads();

    mgh3(P0h, P0l, P1h, P1l, F32, t);
    __syncthreads();

    pack_from_smem(F32, P0h, P0l, t);
    stage_pack_gmem(W_w, P1h, P1l, t);
    __syncthreads();
    if (t < CI) {
        float b0 = dot_packed(P1h, P1l, t, sv_c);
        float sc = sv_scale[t];
        g_bvec[bb * CI + t] = sc * (b0 + W_b[t]) + bn_beta[t] - bn_mean[t] * sc;
    }

    mgh3_final(P1h, P1l, P0h, P0l,
               g_Ah2 + (size_t)bb * CI * 64, g_Al2 + (size_t)bb * CI * 64,
               sv_scale, t);
}

// =====================================================================
// Kernel 3: Z = A'' X + b', fp16 3-product + ldmatrix, single wave,
// LOW-REGISTER version. grid (2, 64), 512 threads. Warp tile 32ch x 32px,
// chunks of [32 ch x 128 px] (stride APR=68 uints), 64 chunks.
// acc = 32 regs/thread -> no spills under the 128-reg cap.
// =====================================================================
#define AP_SMEM ((2 * 128 * APR + 4 * 32 * APR) * 4)   // 104448 B

__global__ void __launch_bounds__(512)
apply_kernel(const float* __restrict__ X, float* __restrict__ Z)
{
    extern __shared__ unsigned apsm[];
    unsigned* sAh = apsm;                       // [128][APR]
    unsigned* sAl = sAh + 128 * APR;
    unsigned* sXh[2] = {sAl + 128 * APR, sAl + 128 * APR + 32 * APR};
    unsigned* sXl[2] = {sAl + 128 * APR + 2 * 32 * APR,
                        sAl + 128 * APR + 3 * 32 * APR};

    const int t = threadIdx.x;
    const int lane = t & 31, w = t >> 5;
    const int wr = (w >> 2) * 32;          // ch group (4 of 32)
    const int wc = (w & 3) * 32;           // px group (4 of 32)
    const int qr = lane >> 2, qc = lane & 3;
    const int bb = blockIdx.y;
    const int half0 = blockIdx.x * 2048;

    const uint32_t aAh = s2u(sAh), aAl = s2u(sAl);
    const uint32_t aXh[2] = {s2u(sXh[0]), s2u(sXh[1])};
    const uint32_t aXl[2] = {s2u(sXl[0]), s2u(sXl[1])};

    // ldmatrix offsets
    uint32_t aoffA[2][2];   // [m][ks]; add g*64 bytes in loop
#pragma unroll
    for (int m = 0; m < 2; m++)
#pragma unroll
        for (int ks = 0; ks < 2; ks++)
            aoffA[m][ks] = (uint32_t)((wr + m * 16 + (lane & 15)) * APR + ks * 8) * 4u
                         + (uint32_t)((lane >> 4) & 1) * 16u;
    uint32_t boffB[2][2];   // [ks][j]
#pragma unroll
    for (int ks = 0; ks < 2; ks++)
#pragma unroll
        for (int j = 0; j < 2; j++)
            boffB[ks][j] = (uint32_t)((ks * 16 + (lane & 7) + ((lane >> 3) & 1) * 8) * APR) * 4u
                         + (uint32_t)(wc + j * 16 + ((lane >> 4) & 1) * 8) * 2u;

    // ---- stage A'' hi/lo resident ONCE ----
    {
        const int row = t >> 2, seg = (t & 3) * 16;
        const uint4* Ah = (const uint4*)(g_Ah2 + ((size_t)bb * CI + row) * 64 + seg);
        const uint4* Al = (const uint4*)(g_Al2 + ((size_t)bb * CI + row) * 64 + seg);
#pragma unroll
        for (int j = 0; j < 4; j++) {
            *(uint4*)&sAh[row * APR + seg + 4 * j] = Ah[j];
            *(uint4*)&sAl[row * APR + seg + 4 * j] = Al[j];
        }
    }

    float bias[2][2];
#pragma unroll
    for (int m = 0; m < 2; m++) {
        bias[m][0] = g_bvec[bb * CI + wr + m * 16 + qr];
        bias[m][1] = g_bvec[bb * CI + wr + m * 16 + qr + 8];
    }

    const float* Xb = X + (size_t)bb * CI * NPIX;
    float* Zb = Z + (size_t)bb * CI * NPIX;

    // X loader: warp w -> ch rows 2w, 2w+1; lane covers 4 px per row
    const int lpx = lane * 4;

    float acc[2][4][4];
#pragma unroll
    for (int m = 0; m < 2; m++)
#pragma unroll
        for (int n = 0; n < 4; n++)
#pragma unroll
            for (int r = 0; r < 4; r++) acc[m][n][r] = 0.f;

    // preload chunk 0 (subtile 0, channels 0..31)
    {
        const float* se = Xb + (size_t)(2 * w) * NPIX + half0 + lpx;
        const float* so = se + NPIX;
        float4 e = *(const float4*)(se);
        float4 o = *(const float4*)(so);
        unsigned h0, l0, h1, l1, h2, l2, h3, l3;
        split2(e.x, e.y, h0, l0); split2(e.z, e.w, h1, l1);
        split2(o.x, o.y, h2, l2); split2(o.z, o.w, h3, l3);
        *(uint2*)&sXh[0][(2 * w) * APR + lane * 2]     = make_uint2(h0, h1);
        *(uint2*)&sXh[0][(2 * w + 1) * APR + lane * 2] = make_uint2(h2, h3);
        *(uint2*)&sXl[0][(2 * w) * APR + lane * 2]     = make_uint2(l0, l1);
        *(uint2*)&sXl[0][(2 * w + 1) * APR + lane * 2] = make_uint2(l2, l3);
    }
    __syncthreads();

    // 64 chunks: c -> subtile s = c>>2 (128 px), k-chunk g = c&3 (32 ch)
    for (int c = 0; c < 64; c++) {
        const int b = c & 1;
        const int g = c & 3;

        float4 ne, no;
        if (c < 63) {
            const int ng = (c + 1) & 3, ns = (c + 1) >> 2;
            const float* se = Xb + (size_t)(ng * 32 + 2 * w) * NPIX + half0 + ns * 128 + lpx;
            ne = *(const float4*)(se);
            no = *(const float4*)(se + NPIX);
        }

        const uint32_t gOff = (uint32_t)g * 64u;
#pragma unroll
        for (int ks = 0; ks < 2; ks++) {
            unsigned Ahf[2][4], Alf[2][4];
#pragma unroll
            for (int m = 0; m < 2; m++) {
                LDSM_X4(Ahf[m], aAh + aoffA[m][ks] + gOff);
                LDSM_X4(Alf[m], aAl + aoffA[m][ks] + gOff);
            }
#pragma unroll
            for (int j = 0; j < 2; j++) {
                unsigned BH[4], BL[4];
                LDSM_X4T(BH, aXh[b] + boffB[ks][j]);
                LDSM_X4T(BL, aXl[b] + boffB[ks][j]);
                unsigned B0h[2] = {BH[0], BH[1]}, B1h[2] = {BH[2], BH[3]};
                unsigned B0l[2] = {BL[0], BL[1]}, B1l[2] = {BL[2], BL[3]};
#pragma unroll
                for (int m = 0; m < 2; m++) {
                    mmah(acc[m][2 * j],     Ahf[m], B0h);
                    mmah(acc[m][2 * j],     Ahf[m], B0l);
                    mmah(acc[m][2 * j],     Alf[m], B0h);
                    mmah(acc[m][2 * j + 1], Ahf[m], B1h);
                    mmah(acc[m][2 * j + 1], Ahf[m], B1l);
                    mmah(acc[m][2 * j + 1], Alf[m], B1h);
                }
            }
        }

        if (c < 63) {
            unsigned h0, l0, h1, l1, h2, l2, h3, l3;
            split2(ne.x, ne.y, h0, l0); split2(ne.z, ne.w, h1, l1);
            split2(no.x, no.y, h2, l2); split2(no.z, no.w, h3, l3);
            *(uint2*)&sXh[b ^ 1][(2 * w) * APR + lane * 2]     = make_uint2(h0, h1);
            *(uint2*)&sXh[b ^ 1][(2 * w + 1) * APR + lane * 2] = make_uint2(h2, h3);
            *(uint2*)&sXl[b ^ 1][(2 * w) * APR + lane * 2]     = make_uint2(l0, l1);
            *(uint2*)&sXl[b ^ 1][(2 * w + 1) * APR + lane * 2] = make_uint2(l2, l3);
        }
        __syncthreads();

        if (g == 3) {   // end of px-subtile: epilogue
            const int px0 = half0 + (c >> 2) * 128;
#pragma unroll
            for (int m = 0; m < 2; m++) {
                const int r0 = wr + m * 16 + qr;
#pragma unroll
                for (int n = 0; n < 4; n++) {
                    const int c0 = px0 + wc + n * 8 + qc * 2;
                    *(float2*)(Zb + (size_t)r0 * NPIX + c0) =
                        make_float2(acc[m][n][0] + bias[m][0], acc[m][n][1] + bias[m][0]);
                    *(float2*)(Zb + (size_t)(r0 + 8) * NPIX + c0) =
                        make_float2(acc[m][n][2] + bias[m][1], acc[m][n][3] + bias[m][1]);
                }
            }
#pragma unroll
            for (int m = 0; m < 2; m++)
#pragma unroll
                for (int n = 0; n < 4; n++)
#pragma unroll
                    for (int r = 0; r < 4; r++) acc[m][n][r] = 0.f;
        }
    }
}

// =====================================================================
extern "C" void kernel_launch(void* const* d_in, const int* in_sizes, int n_in,
                              void* d_out, int out_size)
{
    (void)in_sizes; (void)n_in; (void)out_size;
    const float* x        = (const float*)d_in[0];
    const float* theta_w  = (const float*)d_in[1];
    const float* theta_b  = (const float*)d_in[2];
    const float* phi_w    = (const float*)d_in[3];
    const float* phi_b    = (const float*)d_in[4];
    const float* g_w      = (const float*)d_in[5];
    const float* g_b      = (const float*)d_in[6];
    const float* W_w      = (const float*)d_in[7];
    const float* W_b      = (const float*)d_in[8];
    const float* bn_gamma = (const float*)d_in[9];
    const float* bn_beta  = (const float*)d_in[10];
    const float* bn_mean  = (const float*)d_in[11];
    const float* bn_var   = (const float*)d_in[12];
    float* out = (float*)d_out;

    cudaFuncSetAttribute(chain_kernel,
                         cudaFuncAttributeMaxDynamicSharedMemorySize, CH_SMEM);
    cudaFuncSetAttribute(apply_kernel,
                         cudaFuncAttributeMaxDynamicSharedMemorySize, AP_SMEM);

    gram_kernel<<<dim3(KSPLIT, NB), 256>>>(x);
    chain_kernel<<<NB, 256, CH_SMEM>>>(theta_w, theta_b, phi_w, phi_b,
                                       g_w, g_b, W_w, W_b,
                                       bn_gamma, bn_beta, bn_mean, bn_var);
    apply_kernel<<<dim3(2, NB), 512, AP_SMEM>>>(x, out);
}

// round 13
// speedup vs baseline: 1.1773x; 1.1773x over previous
#include <cuda_runtime.h>
#include <cuda_fp16.h>
#include <cstdint>
#include <math.h>

// Problem constants:
//  x: [16, 512, 64, 64] fp32 == [64 batches][128 ch][4096 px] contiguous
#define NB     64
#define CI     128
#define NPIX   4096
#define KSPLIT 8                 // gram K-split CTAs per batch (K=512 each)
#define GPR    12                // gram pair stride (8 pairs + 4)  [48B, ldsm-cf]
#define APR    68                // packed pair stride (64 pairs + 4) [272B, ldsm-cf]
#define F32S   132               // chain fp32 scratch stride

// ---------------- fp16 helpers ----------------
__device__ __forceinline__ void split2(float a, float b, unsigned& hu, unsigned& lu) {
    __half2 h2 = __float22half2_rn(make_float2(a, b));
    float2 hf = __half22float2(h2);
    __half2 l2 = __float22half2_rn(make_float2(a - hf.x, b - hf.y));
    hu = *(unsigned*)&h2;
    lu = *(unsigned*)&l2;
}
__device__ __forceinline__ void split2s2(float a, float b, unsigned& hu, unsigned& lu) {
    __half2 h2 = __float22half2_rn(make_float2(a, b));
    float2 hf = __half22float2(h2);
    __half2 l2 = __float22half2_rn(make_float2((a - hf.x) * 2.0f, (b - hf.y) * 2.0f));
    hu = *(unsigned*)&h2;
    lu = *(unsigned*)&l2;
}

// D += A(16x16,row,f16) * B(16x8,col,f16)  fp32-accum
__device__ __forceinline__ void mmah(float* d, const unsigned* a, const unsigned* b) {
    asm volatile(
        "mma.sync.aligned.m16n8k16.row.col.f32.f16.f16.f32 "
        "{%0,%1,%2,%3}, {%4,%5,%6,%7}, {%8,%9}, {%0,%1,%2,%3};"
        : "+f"(d[0]), "+f"(d[1]), "+f"(d[2]), "+f"(d[3])
        : "r"(a[0]), "r"(a[1]), "r"(a[2]), "r"(a[3]), "r"(b[0]), "r"(b[1]));
}

__device__ __forceinline__ uint32_t s2u(const void* p) {
    return (uint32_t)__cvta_generic_to_shared(p);
}
#define LDSM_X4(r, addr) \
    asm volatile("ldmatrix.sync.aligned.m8n8.x4.shared.b16 {%0,%1,%2,%3}, [%4];" \
        : "=r"((r)[0]), "=r"((r)[1]), "=r"((r)[2]), "=r"((r)[3]) : "r"(addr))
#define LDSM_X4T(r, addr) \
    asm volatile("ldmatrix.sync.aligned.m8n8.x4.trans.shared.b16 {%0,%1,%2,%3}, [%4];" \
        : "=r"((r)[0]), "=r"((r)[1]), "=r"((r)[2]), "=r"((r)[3]) : "r"(addr))

// ---------------- scratch ----------------
__device__ float    g_Gpart[NB * KSPLIT * CI * CI]; // partial E (G = (E+E^T)/2)
__device__ float    g_spart[NB * KSPLIT * CI];      // partial row sums
__device__ unsigned g_Ah2[NB * CI * 64];            // A'' fp16-hi, half2 pairs
__device__ unsigned g_Al2[NB * CI * 64];            // A'' fp16-lo, half2 pairs
__device__ float    g_bvec[NB * CI];                // folded bias b'

// =====================================================================
// Kernel 1 (round-11 proven, 68us): partial E = H H^T + H (2L)^T.
// =====================================================================
__global__ void __launch_bounds__(256, 2)
gram_kernel(const float* __restrict__ X)
{
    __shared__ unsigned sH[2][128 * GPR];
    __shared__ unsigned sL[2][128 * GPR];
    __shared__ float sred[256];

    const int t = threadIdx.x;
    const int lane = t & 31, w = t >> 5;
    const int wr = (w >> 2) * 64, wc = (w & 3) * 32;
    const int qr = lane >> 2, qc = lane & 3;
    const int kc = blockIdx.x, bb = blockIdx.y;

    const float* Xb = X + (size_t)bb * CI * NPIX + (size_t)kc * 512;
    const int lrow = t >> 1, lp4 = (t & 1) * 4;
    const int sbase = lrow * GPR + lp4;
    const float* Xr = Xb + (size_t)lrow * NPIX + lp4 * 2;

    const uint32_t aH[2] = {s2u(sH[0]), s2u(sH[1])};
    const uint32_t aL[2] = {s2u(sL[0]), s2u(sL[1])};

    uint32_t aoffA[4], boffB[2];
#pragma unroll
    for (int m = 0; m < 4; m++)
        aoffA[m] = (uint32_t)((wr + m * 16 + (lane & 15)) * GPR) * 4u
                 + (uint32_t)((lane >> 4) & 1) * 16u;
#pragma unroll
    for (int j = 0; j < 2; j++)
        boffB[j] = (uint32_t)((wc + j * 16 + (lane & 7) + ((lane >> 4) & 1) * 8) * GPR) * 4u
                 + (uint32_t)((lane >> 3) & 1) * 16u;

    float acc[4][4][4];
#pragma unroll
    for (int m = 0; m < 4; m++)
#pragma unroll
        for (int n = 0; n < 4; n++)
#pragma unroll
            for (int r = 0; r < 4; r++) acc[m][n][r] = 0.f;
    float mysum = 0.f;

    {
        float4 v0 = *(const float4*)(Xr);
        float4 v1 = *(const float4*)(Xr + 4);
        unsigned hu[4], lu[4];
        split2s2(v0.x, v0.y, hu[0], lu[0]);
        split2s2(v0.z, v0.w, hu[1], lu[1]);
        split2s2(v1.x, v1.y, hu[2], lu[2]);
        split2s2(v1.z, v1.w, hu[3], lu[3]);
        mysum += v0.x + v0.y + v0.z + v0.w + v1.x + v1.y + v1.z + v1.w;
        *(uint4*)&sH[0][sbase] = make_uint4(hu[0], hu[1], hu[2], hu[3]);
        *(uint4*)&sL[0][sbase] = make_uint4(lu[0], lu[1], lu[2], lu[3]);
    }
    __syncthreads();

    for (int ch = 0; ch < 32; ch++) {
        const int b = ch & 1;
        float4 n0, n1;
        if (ch < 31) {
            n0 = *(const float4*)(Xr + (ch + 1) * 16);
            n1 = *(const float4*)(Xr + (ch + 1) * 16 + 4);
        }

        unsigned Af[4][4];
#pragma unroll
        for (int m = 0; m < 4; m++) LDSM_X4(Af[m], aH[b] + aoffA[m]);
#pragma unroll
        for (int j = 0; j < 2; j++) {
            unsigned BH[4], BL[4];
            LDSM_X4(BH, aH[b] + boffB[j]);
            LDSM_X4(BL, aL[b] + boffB[j]);
            unsigned B0h[2] = {BH[0], BH[1]}, B1h[2] = {BH[2], BH[3]};
            unsigned B0l[2] = {BL[0], BL[1]}, B1l[2] = {BL[2], BL[3]};
#pragma unroll
            for (int m = 0; m < 4; m++) {
                mmah(acc[m][2 * j],     Af[m], B0h);
                mmah(acc[m][2 * j],     Af[m], B0l);
                mmah(acc[m][2 * j + 1], Af[m], B1h);
                mmah(acc[m][2 * j + 1], Af[m], B1l);
            }
        }

        if (ch < 31) {
            unsigned hu[4], lu[4];
            split2s2(n0.x, n0.y, hu[0], lu[0]);
            split2s2(n0.z, n0.w, hu[1], lu[1]);
            split2s2(n1.x, n1.y, hu[2], lu[2]);
            split2s2(n1.z, n1.w, hu[3], lu[3]);
            mysum += n0.x + n0.y + n0.z + n0.w + n1.x + n1.y + n1.z + n1.w;
            *(uint4*)&sH[b ^ 1][sbase] = make_uint4(hu[0], hu[1], hu[2], hu[3]);
            *(uint4*)&sL[b ^ 1][sbase] = make_uint4(lu[0], lu[1], lu[2], lu[3]);
        }
        __syncthreads();
    }

    sred[t] = mysum;
    __syncthreads();
    if (t < 128)
        g_spart[(bb * KSPLIT + kc) * CI + t] = sred[2 * t] + sred[2 * t + 1];

    float* P = g_Gpart + ((size_t)(bb * KSPLIT + kc)) * CI * CI;
#pragma unroll
    for (int m = 0; m < 4; m++) {
        const int r0 = wr + m * 16 + qr;
#pragma unroll
        for (int n = 0; n < 4; n++) {
            const int c0 = wc + n * 8 + qc * 2;
            *(float2*)(P + (size_t)r0 * CI + c0)       = make_float2(acc[m][n][0], acc[m][n][1]);
            *(float2*)(P + (size_t)(r0 + 8) * CI + c0) = make_float2(acc[m][n][2], acc[m][n][3]);
        }
    }
}

// =====================================================================
// Kernel 2: chain, tensorized (round-10/11 proven, unchanged).
// =====================================================================
#define CH_PK   (128 * APR * 4)
#define CH_OF32 (4 * CH_PK)
#define CH_SMEM (CH_OF32 + 128 * F32S * 4)

__device__ __forceinline__ void mgh3(const unsigned* __restrict__ Ah,
                                     const unsigned* __restrict__ Al,
                                     const unsigned* __restrict__ Bh,
                                     const unsigned* __restrict__ Bl,
                                     float* __restrict__ O, int t)
{
    const int lane = t & 31, w = t >> 5;
    const int wr = (w >> 2) * 64, wc = (w & 3) * 32;
    const int qr = lane >> 2, qc = lane & 3;
    float acc[4][4][4];
#pragma unroll
    for (int m = 0; m < 4; m++)
#pragma unroll
        for (int n = 0; n < 4; n++)
#pragma unroll
            for (int r = 0; r < 4; r++) acc[m][n][r] = 0.f;

#pragma unroll
    for (int s = 0; s < 8; s++) {
        const int kp = s * 8;
        unsigned Afh[4][4], Afl[4][4];
#pragma unroll
        for (int m = 0; m < 4; m++) {
            const int ar = wr + m * 16 + qr;
            Afh[m][0] = Ah[ar * APR + kp + qc];
            Afh[m][1] = Ah[(ar + 8) * APR + kp + qc];
            Afh[m][2] = Ah[ar * APR + kp + qc + 4];
            Afh[m][3] = Ah[(ar + 8) * APR + kp + qc + 4];
            Afl[m][0] = Al[ar * APR + kp + qc];
            Afl[m][1] = Al[(ar + 8) * APR + kp + qc];
            Afl[m][2] = Al[ar * APR + kp + qc + 4];
            Afl[m][3] = Al[(ar + 8) * APR + kp + qc + 4];
        }
#pragma unroll
        for (int n = 0; n < 4; n++) {
            const int br = wc + n * 8 + qr;
            unsigned Bfh[2] = {Bh[br * APR + kp + qc], Bh[br * APR + kp + qc + 4]};
            unsigned Bfl[2] = {Bl[br * APR + kp + qc], Bl[br * APR + kp + qc + 4]};
#pragma unroll
            for (int m = 0; m < 4; m++) {
                mmah(acc[m][n], Afh[m], Bfh);
                mmah(acc[m][n], Afh[m], Bfl);
                mmah(acc[m][n], Afl[m], Bfh);
            }
        }
    }
#pragma unroll
    for (int m = 0; m < 4; m++) {
        const int r0 = wr + m * 16 + qr;
#pragma unroll
        for (int n = 0; n < 4; n++) {
            const int c0 = wc + n * 8 + qc * 2;
            *(float2*)&O[r0 * F32S + c0]       = make_float2(acc[m][n][0], acc[m][n][1]);
            *(float2*)&O[(r0 + 8) * F32S + c0] = make_float2(acc[m][n][2], acc[m][n][3]);
        }
    }
}

__device__ __forceinline__ void mgh3_final(const unsigned* __restrict__ Ah,
                                           const unsigned* __restrict__ Al,
                                           const unsigned* __restrict__ Bh,
                                           const unsigned* __restrict__ Bl,
                                           unsigned* __restrict__ gAh,
                                           unsigned* __restrict__ gAl,
                                           const float* __restrict__ scale, int t)
{
    const int lane = t & 31, w = t >> 5;
    const int wr = (w >> 2) * 64, wc = (w & 3) * 32;
    const int qr = lane >> 2, qc = lane & 3;
    float acc[4][4][4];
#pragma unroll
    for (int m = 0; m < 4; m++)
#pragma unroll
        for (int n = 0; n < 4; n++)
#pragma unroll
            for (int r = 0; r < 4; r++) acc[m][n][r] = 0.f;

#pragma unroll
    for (int s = 0; s < 8; s++) {
        const int kp = s * 8;
        unsigned Afh[4][4], Afl[4][4];
#pragma unroll
        for (int m = 0; m < 4; m++) {
            const int ar = wr + m * 16 + qr;
            Afh[m][0] = Ah[ar * APR + kp + qc];
            Afh[m][1] = Ah[(ar + 8) * APR + kp + qc];
            Afh[m][2] = Ah[ar * APR + kp + qc + 4];
            Afh[m][3] = Ah[(ar + 8) * APR + kp + qc + 4];
            Afl[m][0] = Al[ar * APR + kp + qc];
            Afl[m][1] = Al[(ar + 8) * APR + kp + qc];
            Afl[m][2] = Al[ar * APR + kp + qc + 4];
            Afl[m][3] = Al[(ar + 8) * APR + kp + qc + 4];
        }
#pragma unroll
        for (int n = 0; n < 4; n++) {
            const int br = wc + n * 8 + qr;
            unsigned Bfh[2] = {Bh[br * APR + kp + qc], Bh[br * APR + kp + qc + 4]};
            unsigned Bfl[2] = {Bl[br * APR + kp + qc], Bl[br * APR + kp + qc + 4]};
#pragma unroll
            for (int m = 0; m < 4; m++) {
                mmah(acc[m][n], Afh[m], Bfh);
                mmah(acc[m][n], Afh[m], Bfl);
                mmah(acc[m][n], Afl[m], Bfh);
            }
        }
    }
#pragma unroll
    for (int m = 0; m < 4; m++) {
        const int r0 = wr + m * 16 + qr;
        const float s0 = scale[r0], s1 = scale[r0 + 8];
#pragma unroll
        for (int n = 0; n < 4; n++) {
            const int c0 = wc + n * 8 + qc * 2;
            float v0 = s0 * acc[m][n][0] + ((r0 == c0) ? 1.f : 0.f);
            float v1 = s0 * acc[m][n][1] + ((r0 == c0 + 1) ? 1.f : 0.f);
            float v2 = s1 * acc[m][n][2] + ((r0 + 8 == c0) ? 1.f : 0.f);
            float v3 = s1 * acc[m][n][3] + ((r0 + 8 == c0 + 1) ? 1.f : 0.f);
            unsigned hu, lu;
            split2(v0, v1, hu, lu);
            gAh[r0 * 64 + c0 / 2] = hu;
            gAl[r0 * 64 + c0 / 2] = lu;
            split2(v2, v3, hu, lu);
            gAh[(r0 + 8) * 64 + c0 / 2] = hu;
            gAl[(r0 + 8) * 64 + c0 / 2] = lu;
        }
    }
}

__device__ __forceinline__ void stage_pack_gmem(const float* __restrict__ src,
                                                unsigned* __restrict__ Ph,
                                                unsigned* __restrict__ Pl, int t)
{
    const int row = t >> 1, seg = (t & 1) * 64;
    const int base = row * APR + seg / 2;
    const float4* s4 = (const float4*)(src + row * CI + seg);
#pragma unroll
    for (int j = 0; j < 16; j++) {
        float4 v = s4[j];
        unsigned h0, l0, h1, l1;
        split2(v.x, v.y, h0, l0);
        split2(v.z, v.w, h1, l1);
        *(uint2*)&Ph[base + 2 * j] = make_uint2(h0, h1);
        *(uint2*)&Pl[base + 2 * j] = make_uint2(l0, l1);
    }
}

__device__ __forceinline__ void pack_from_smem(const float* __restrict__ F,
                                               unsigned* __restrict__ Ph,
                                               unsigned* __restrict__ Pl, int t)
{
    const int row = t >> 1, seg = (t & 1) * 64;
    const int base = row * APR + seg / 2;
    const float* fr = F + row * F32S + seg;
#pragma unroll
    for (int j = 0; j < 32; j++) {
        float2 v = *(const float2*)(fr + 2 * j);
        unsigned h, l;
        split2(v.x, v.y, h, l);
        Ph[base + j] = h;
        Pl[base + j] = l;
    }
}

__device__ __forceinline__ float dot_packed(const unsigned* __restrict__ Ph,
                                            const unsigned* __restrict__ Pl,
                                            int row, const float* __restrict__ s)
{
    float acc = 0.f;
#pragma unroll 8
    for (int p = 0; p < 64; p++) {
        float2 hf = __half22float2(*(const __half2*)&Ph[row * APR + p]);
        float2 lf = __half22float2(*(const __half2*)&Pl[row * APR + p]);
        acc += (hf.x + lf.x) * s[2 * p] + (hf.y + lf.y) * s[2 * p + 1];
    }
    return acc;
}

__global__ void __launch_bounds__(256)
chain_kernel(const float* __restrict__ theta_w, const float* __restrict__ theta_b,
             const float* __restrict__ phi_w,   const float* __restrict__ phi_b,
             const float* __restrict__ g_w,     const float* __restrict__ g_b,
             const float* __restrict__ W_w,     const float* __restrict__ W_b,
             const float* __restrict__ bn_gamma, const float* __restrict__ bn_beta,
             const float* __restrict__ bn_mean,  const float* __restrict__ bn_var)
{
    extern __shared__ char csm[];
    unsigned* P0h = (unsigned*)(csm);
    unsigned* P0l = (unsigned*)(csm + CH_PK);
    unsigned* P1h = (unsigned*)(csm + 2 * CH_PK);
    unsigned* P1l = (unsigned*)(csm + 3 * CH_PK);
    float*    F32 = (float*)(csm + CH_OF32);

    __shared__ float sv_s[CI], sv_u[CI], sv_q[CI], sv_tb[CI],
                     sv_gb[CI], sv_c[CI], sv_scale[CI];

    const int t  = threadIdx.x;
    const int bb = blockIdx.x;

    const float* Gp = g_Gpart + (size_t)bb * KSPLIT * CI * CI;
    for (int idx = t; idx < CI * CI; idx += 256) {
        float v = 0.f;
#pragma unroll
        for (int ks = 0; ks < KSPLIT; ks++) v += Gp[ks * CI * CI + idx];
        F32[(idx >> 7) * F32S + (idx & 127)] = v;
    }
    if (t < CI) {
        float v = 0.f;
#pragma unroll
        for (int ks = 0; ks < KSPLIT; ks++) v += g_spart[(bb * KSPLIT + ks) * CI + t];
        sv_s[t]  = v;
        sv_tb[t] = theta_b[t];
        sv_gb[t] = g_b[t];
        sv_scale[t] = bn_gamma[t] * rsqrtf(bn_var[t] + 1e-5f);
    }
    stage_pack_gmem(theta_w, P1h, P1l, t);
    __syncthreads();

    for (int i = t; i < 8256; i += 256) {
        int r = (int)((sqrtf(8.0f * (float)i + 1.0f) - 1.0f) * 0.5f);
        if ((r + 1) * (r + 2) / 2 <= i) r++;
        if (r * (r + 1) / 2 > i) r--;
        int c = i - r * (r + 1) / 2;
        float a = F32[r * F32S + c], b = F32[c * F32S + r];
        float g = 0.5f * (a + b);
        F32[r * F32S + c] = g;
        F32[c * F32S + r] = g;
    }
    if (t < CI)
        sv_q[t] = dot_packed(P1h, P1l, t, sv_s) + 4096.0f * sv_tb[t];
    __syncthreads();

    pack_from_smem(F32, P0h, P0l, t);
    __syncthreads();

    mgh3(P1h, P1l, P0h, P0l, F32, t);
    __syncthreads();

    pack_from_smem(F32, P0h, P0l, t);
    stage_pack_gmem(phi_w, P1h, P1l, t);
    __syncthreads();
    if (t < CI)
        sv_u[t] = dot_packed(P1h, P1l, t, sv_s);
    __syncthreads();

    mgh3(P1h, P1l, P0h, P0l, F32, t);
    __syncthreads();

    if (t < CI) {
        const float w1 = sv_u[t];
        const float w2 = phi_b[t];
        float* rowp = F32 + t * F32S;
        float mx = -1e30f;
#pragma unroll 8
        for (int d = 0; d < 128; d++) {
            float v = rowp[d] + w1 * sv_tb[d] + w2 * sv_q[d];
            rowp[d] = v;
            mx = fmaxf(mx, v);
        }
        float ssum = 0.f;
#pragma unroll 8
        for (int d = 0; d < 128; d++) {
            float ev = expf(rowp[d] - mx);
            rowp[d] = ev;
            ssum += ev;
        }
        const float inv = 1.0f / ssum;
        float cacc = 0.f;
#pragma unroll
        for (int p = 0; p < 64; p++) {
            float f0 = rowp[2 * p] * inv;
            float f1 = rowp[2 * p + 1] * inv;
            cacc += f0 * sv_gb[2 * p] + f1 * sv_gb[2 * p + 1];
            unsigned h, l;
            split2(f0, f1, h, l);
            P1h[t * APR + p] = h;
            P1l[t * APR + p] = l;
        }
        sv_c[t] = cacc;
    }
    __syncthreads();

    for (int idx = t; idx < CI * CI; idx += 256)
        F32[(idx >> 7) * F32S + (idx & 127)] = g_w[idx];
    __syncthreads();
    {
        const int k = t >> 1, d0 = (t & 1) * 64;
        const int base = k * APR + d0 / 2;
#pragma unroll
        for (int p = 0; p < 32; p++) {
            const int d = d0 + 2 * p;
            unsigned h, l;
            split2(F32[d * F32S + k], F32[(d + 1) * F32S + k], h, l);
            P0h[base + p] = h;
            P0l[base + p] = l;
        }
    }
    __syncthreads();

    mgh3(P0h, P0l, P1h, P1l, F32, t);
    __syncthreads();

    pack_from_smem(F32, P0h, P0l, t);
    stage_pack_gmem(W_w, P1h, P1l, t);
    __syncthreads();
    if (t < CI) {
        float b0 = dot_packed(P1h, P1l, t, sv_c);
        float sc = sv_scale[t];
        g_bvec[bb * CI + t] = sc * (b0 + W_b[t]) + bn_beta[t] - bn_mean[t] * sc;
    }

    mgh3_final(P1h, P1l, P0h, P0l,
               g_Ah2 + (size_t)bb * CI * 64, g_Al2 + (size_t)bb * CI * 64,
               sv_scale, t);
}

// =====================================================================
// Kernel 3: Z = A'' X + b', fp16 3-product + ldmatrix, GRAM-SHAPED:
// 256 threads, 2 CTAs/SM. grid (32, 64), CTA tile 128ch x 128px.
// A'' resident (69.6KB); X: 8 chunks of [16 ch x 128 px] double-buffered.
// Warp grid 4x2, warp tile 32ch x 64px (48 MMA / 12 LDSM per chunk).
// =====================================================================
#define AP_SMEM ((2 * 128 * APR + 4 * 16 * APR) * 4)   // 87040 B

__global__ void __launch_bounds__(256, 2)
apply_kernel(const float* __restrict__ X, float* __restrict__ Z)
{
    extern __shared__ unsigned apsm[];
    unsigned* sAh = apsm;                        // [128][APR]
    unsigned* sAl = sAh + 128 * APR;
    unsigned* sXh[2] = {sAl + 128 * APR, sAl + 128 * APR + 16 * APR};
    unsigned* sXl[2] = {sAl + 128 * APR + 2 * 16 * APR,
                        sAl + 128 * APR + 3 * 16 * APR};

    const int t = threadIdx.x;
    const int lane = t & 31, w = t >> 5;
    const int wr = (w >> 1) * 32;          // 4 ch-groups of 32
    const int wc = (w & 1) * 64;           // 2 px-groups of 64
    const int qr = lane >> 2, qc = lane & 3;
    const int bb = blockIdx.y;
    const int px0 = blockIdx.x * 128;

    const uint32_t aAh = s2u(sAh), aAl = s2u(sAl);
    const uint32_t aXh[2] = {s2u(sXh[0]), s2u(sXh[1])};
    const uint32_t aXl[2] = {s2u(sXl[0]), s2u(sXl[1])};

    // ldmatrix offsets
    uint32_t aoffA[2];          // [m]; add g*32 bytes per chunk
#pragma unroll
    for (int m = 0; m < 2; m++)
        aoffA[m] = (uint32_t)((wr + m * 16 + (lane & 15)) * APR) * 4u
                 + (uint32_t)((lane >> 4) & 1) * 16u;
    uint32_t boffB[4];          // [j], 16 px each (round-11-proven trans pattern)
#pragma unroll
    for (int j = 0; j < 4; j++)
        boffB[j] = (uint32_t)(((lane & 7) + ((lane >> 3) & 1) * 8) * APR) * 4u
                 + (uint32_t)(wc + j * 16 + ((lane >> 4) & 1) * 8) * 2u;

    // ---- stage A'' hi/lo resident ONCE ----
    {
        const int row = t >> 1, seg = (t & 1) * 32;
        const uint4* Ah = (const uint4*)(g_Ah2 + ((size_t)bb * CI + row) * 64 + seg);
        const uint4* Al = (const uint4*)(g_Al2 + ((size_t)bb * CI + row) * 64 + seg);
#pragma unroll
        for (int j = 0; j < 8; j++) {
            *(uint4*)&sAh[row * APR + seg + 4 * j] = Ah[j];
            *(uint4*)&sAl[row * APR + seg + 4 * j] = Al[j];
        }
    }

    float bias[2][2];
#pragma unroll
    for (int m = 0; m < 2; m++) {
        bias[m][0] = g_bvec[bb * CI + wr + m * 16 + qr];
        bias[m][1] = g_bvec[bb * CI + wr + m * 16 + qr + 8];
    }

    const float* Xb = X + (size_t)bb * CI * NPIX;
    float* Zb = Z + (size_t)bb * CI * NPIX;

    // X loader: thread t -> chunk-row rr = t>>4 (0..15), px (t&15)*8
    const int rr = t >> 4, lpx = (t & 15) * 8;
    const int xsb = rr * APR + (t & 15) * 4;

    float acc[2][8][4];
#pragma unroll
    for (int m = 0; m < 2; m++)
#pragma unroll
        for (int n = 0; n < 8; n++)
#pragma unroll
            for (int r = 0; r < 4; r++) acc[m][n][r] = 0.f;

    // preload chunk 0 (channels 0..15)
    {
        const float* src = Xb + (size_t)rr * NPIX + px0 + lpx;
        float4 v0 = *(const float4*)(src), v1 = *(const float4*)(src + 4);
        unsigned hu[4], lu[4];
        split2(v0.x, v0.y, hu[0], lu[0]);
        split2(v0.z, v0.w, hu[1], lu[1]);
        split2(v1.x, v1.y, hu[2], lu[2]);
        split2(v1.z, v1.w, hu[3], lu[3]);
        *(uint4*)&sXh[0][xsb] = make_uint4(hu[0], hu[1], hu[2], hu[3]);
        *(uint4*)&sXl[0][xsb] = make_uint4(lu[0], lu[1], lu[2], lu[3]);
    }
    __syncthreads();

    // 8 k-chunks of 16 channels
    for (int g = 0; g < 8; g++) {
        const int b = g & 1;
        float4 n0, n1;
        if (g < 7) {
            const float* src = Xb + (size_t)((g + 1) * 16 + rr) * NPIX + px0 + lpx;
            n0 = *(const float4*)(src);
            n1 = *(const float4*)(src + 4);
        }

        const uint32_t gOff = (uint32_t)g * 32u;   // 16 k = 8 pairs = 32 bytes
        unsigned Ahf[2][4], Alf[2][4];
#pragma unroll
        for (int m = 0; m < 2; m++) {
            LDSM_X4(Ahf[m], aAh + aoffA[m] + gOff);
            LDSM_X4(Alf[m], aAl + aoffA[m] + gOff);
        }
#pragma unroll
        for (int j = 0; j < 4; j++) {
            unsigned BH[4], BL[4];
            LDSM_X4T(BH, aXh[b] + boffB[j]);
            LDSM_X4T(BL, aXl[b] + boffB[j]);
            unsigned B0h[2] = {BH[0], BH[1]}, B1h[2] = {BH[2], BH[3]};
            unsigned B0l[2] = {BL[0], BL[1]}, B1l[2] = {BL[2], BL[3]};
#pragma unroll
            for (int m = 0; m < 2; m++) {
                mmah(acc[m][2 * j],     Ahf[m], B0h);
                mmah(acc[m][2 * j],     Ahf[m], B0l);
                mmah(acc[m][2 * j],     Alf[m], B0h);
                mmah(acc[m][2 * j + 1], Ahf[m], B1h);
                mmah(acc[m][2 * j + 1], Ahf[m], B1l);
                mmah(acc[m][2 * j + 1], Alf[m], B1h);
            }
        }

        if (g < 7) {
            unsigned hu[4], lu[4];
            split2(n0.x, n0.y, hu[0], lu[0]);
            split2(n0.z, n0.w, hu[1], lu[1]);
            split2(n1.x, n1.y, hu[2], lu[2]);
            split2(n1.z, n1.w, hu[3], lu[3]);
            *(uint4*)&sXh[b ^ 1][xsb] = make_uint4(hu[0], hu[1], hu[2], hu[3]);
            *(uint4*)&sXl[b ^ 1][xsb] = make_uint4(lu[0], lu[1], lu[2], lu[3]);
        }
        __syncthreads();
    }

    // ---- epilogue: bias + store ----
#pragma unroll
    for (int m = 0; m < 2; m++) {
        const int r0 = wr + m * 16 + qr;
#pragma unroll
        for (int n = 0; n < 8; n++) {
            const int c0 = px0 + wc + n * 8 + qc * 2;
            *(float2*)(Zb + (size_t)r0 * NPIX + c0) =
                make_float2(acc[m][n][0] + bias[m][0], acc[m][n][1] + bias[m][0]);
            *(float2*)(Zb + (size_t)(r0 + 8) * NPIX + c0) =
                make_float2(acc[m][n][2] + bias[m][1], acc[m][n][3] + bias[m][1]);
        }
    }
}

// =====================================================================
extern "C" void kernel_launch(void* const* d_in, const int* in_sizes, int n_in,
                              void* d_out, int out_size)
{
    (void)in_sizes; (void)n_in; (void)out_size;
    const float* x        = (const float*)d_in[0];
    const float* theta_w  = (const float*)d_in[1];
    const float* theta_b  = (const float*)d_in[2];
    const float* phi_w    = (const float*)d_in[3];
    const float* phi_b    = (const float*)d_in[4];
    const float* g_w      = (const float*)d_in[5];
    const float* g_b      = (const float*)d_in[6];
    const float* W_w      = (const float*)d_in[7];
    const float* W_b      = (const float*)d_in[8];
    const float* bn_gamma = (const float*)d_in[9];
    const float* bn_beta  = (const float*)d_in[10];
    const float* bn_mean  = (const float*)d_in[11];
    const float* bn_var   = (const float*)d_in[12];
    float* out = (float*)d_out;

    cudaFuncSetAttribute(chain_kernel,
                         cudaFuncAttributeMaxDynamicSharedMemorySize, CH_SMEM);
    cudaFuncSetAttribute(apply_kernel,
                         cudaFuncAttributeMaxDynamicSharedMemorySize, AP_SMEM);

    gram_kernel<<<dim3(KSPLIT, NB), 256>>>(x);
    chain_kernel<<<NB, 256, CH_SMEM>>>(theta_w, theta_b, phi_w, phi_b,
                                       g_w, g_b, W_w, W_b,
                                       bn_gamma, bn_beta, bn_mean, bn_var);
    apply_kernel<<<dim3(NPIX / 128, NB), 256, AP_SMEM>>>(x, out);
}

// round 14
// speedup vs baseline: 1.2697x; 1.0785x over previous
#include <cuda_runtime.h>
#include <cuda_fp16.h>
#include <cstdint>
#include <math.h>

// Problem constants:
//  x: [16, 512, 64, 64] fp32 == [64 batches][128 ch][4096 px] contiguous
#define NB     64
#define CI     128
#define NPIX   4096
#define KSPLIT 8                 // gram K-split CTAs per batch (K=512 each)
#define GP2    20                // gram pair stride (16 pairs + 4) [80B, ldsm-cf]
#define APR    68                // packed pair stride (64 pairs + 4) [272B, ldsm-cf]
#define F32S   132               // chain fp32 scratch stride

// ---------------- fp16 helpers ----------------
__device__ __forceinline__ void split2(float a, float b, unsigned& hu, unsigned& lu) {
    __half2 h2 = __float22half2_rn(make_float2(a, b));
    float2 hf = __half22float2(h2);
    __half2 l2 = __float22half2_rn(make_float2(a - hf.x, b - hf.y));
    hu = *(unsigned*)&h2;
    lu = *(unsigned*)&l2;
}
__device__ __forceinline__ void split2s2(float a, float b, unsigned& hu, unsigned& lu) {
    __half2 h2 = __float22half2_rn(make_float2(a, b));
    float2 hf = __half22float2(h2);
    __half2 l2 = __float22half2_rn(make_float2((a - hf.x) * 2.0f, (b - hf.y) * 2.0f));
    hu = *(unsigned*)&h2;
    lu = *(unsigned*)&l2;
}
__device__ __forceinline__ unsigned cvt2(float a, float b) {
    __half2 h2 = __float22half2_rn(make_float2(a, b));
    return *(unsigned*)&h2;
}

// D += A(16x16,row,f16) * B(16x8,col,f16)  fp32-accum
__device__ __forceinline__ void mmah(float* d, const unsigned* a, const unsigned* b) {
    asm volatile(
        "mma.sync.aligned.m16n8k16.row.col.f32.f16.f16.f32 "
        "{%0,%1,%2,%3}, {%4,%5,%6,%7}, {%8,%9}, {%0,%1,%2,%3};"
        : "+f"(d[0]), "+f"(d[1]), "+f"(d[2]), "+f"(d[3])
        : "r"(a[0]), "r"(a[1]), "r"(a[2]), "r"(a[3]), "r"(b[0]), "r"(b[1]));
}

__device__ __forceinline__ uint32_t s2u(const void* p) {
    return (uint32_t)__cvta_generic_to_shared(p);
}
#define LDSM_X4(r, addr) \
    asm volatile("ldmatrix.sync.aligned.m8n8.x4.shared.b16 {%0,%1,%2,%3}, [%4];" \
        : "=r"((r)[0]), "=r"((r)[1]), "=r"((r)[2]), "=r"((r)[3]) : "r"(addr))
#define LDSM_X4T(r, addr) \
    asm volatile("ldmatrix.sync.aligned.m8n8.x4.trans.shared.b16 {%0,%1,%2,%3}, [%4];" \
        : "=r"((r)[0]), "=r"((r)[1]), "=r"((r)[2]), "=r"((r)[3]) : "r"(addr))

// ---------------- scratch ----------------
__device__ float    g_Gpart[NB * KSPLIT * CI * CI]; // partial E (G = (E+E^T)/2)
__device__ float    g_spart[NB * KSPLIT * CI];      // partial row sums
__device__ unsigned g_Ah2[NB * CI * 64];            // A'' fp16-hi, half2 pairs
__device__ unsigned g_Al2[NB * CI * 64];            // A'' fp16-lo, half2 pairs
__device__ float    g_bvec[NB * CI];                // folded bias b'

// =====================================================================
// Kernel 1: partial E = H H^T + H (2L)^T, fp16 + ldmatrix.
// 32-px chunks (16 per CTA) -> half the barriers of round 11.
// grid (KSPLIT, NB), 256 threads, 2 CTAs/SM.
// =====================================================================
__global__ void __launch_bounds__(256, 2)
gram_kernel(const float* __restrict__ X)
{
    __shared__ unsigned sH[2][128 * GP2];
    __shared__ unsigned sL[2][128 * GP2];
    __shared__ float sred[256];

    const int t = threadIdx.x;
    const int lane = t & 31, w = t >> 5;
    const int wr = (w >> 2) * 64, wc = (w & 3) * 32;
    const int qr = lane >> 2, qc = lane & 3;
    const int kc = blockIdx.x, bb = blockIdx.y;

    const float* Xb = X + (size_t)bb * CI * NPIX + (size_t)kc * 512;
    const int lrow = t >> 1;
    const int sbase = lrow * GP2 + (t & 1) * 8;
    const float* Xr = Xb + (size_t)lrow * NPIX + (t & 1) * 16;

    const uint32_t aH[2] = {s2u(sH[0]), s2u(sH[1])};
    const uint32_t aL[2] = {s2u(sL[0]), s2u(sL[1])};

    uint32_t aoffA[4], boffB[2];
#pragma unroll
    for (int m = 0; m < 4; m++)
        aoffA[m] = (uint32_t)((wr + m * 16 + (lane & 15)) * GP2) * 4u
                 + (uint32_t)((lane >> 4) & 1) * 16u;
#pragma unroll
    for (int j = 0; j < 2; j++)
        boffB[j] = (uint32_t)((wc + j * 16 + (lane & 7) + ((lane >> 4) & 1) * 8) * GP2) * 4u
                 + (uint32_t)((lane >> 3) & 1) * 16u;

    float acc[4][4][4];
#pragma unroll
    for (int m = 0; m < 4; m++)
#pragma unroll
        for (int n = 0; n < 4; n++)
#pragma unroll
            for (int r = 0; r < 4; r++) acc[m][n][r] = 0.f;
    float mysum = 0.f;

    // converter for 16 floats -> 8 hi + 8 lo(2x) uints
    {
        float4 v[4];
#pragma unroll
        for (int q = 0; q < 4; q++) v[q] = *(const float4*)(Xr + 4 * q);
        unsigned hu[8], lu[8];
#pragma unroll
        for (int q = 0; q < 4; q++) {
            split2s2(v[q].x, v[q].y, hu[2 * q], lu[2 * q]);
            split2s2(v[q].z, v[q].w, hu[2 * q + 1], lu[2 * q + 1]);
            mysum += v[q].x + v[q].y + v[q].z + v[q].w;
        }
        *(uint4*)&sH[0][sbase]     = make_uint4(hu[0], hu[1], hu[2], hu[3]);
        *(uint4*)&sH[0][sbase + 4] = make_uint4(hu[4], hu[5], hu[6], hu[7]);
        *(uint4*)&sL[0][sbase]     = make_uint4(lu[0], lu[1], lu[2], lu[3]);
        *(uint4*)&sL[0][sbase + 4] = make_uint4(lu[4], lu[5], lu[6], lu[7]);
    }
    __syncthreads();

    for (int ch = 0; ch < 16; ch++) {
        const int b = ch & 1;
        float4 nv[4];
        if (ch < 15) {
#pragma unroll
            for (int q = 0; q < 4; q++)
                nv[q] = *(const float4*)(Xr + (ch + 1) * 32 + 4 * q);
        }

#pragma unroll
        for (int ks = 0; ks < 2; ks++) {
            const uint32_t kOff = (uint32_t)ks * 32u;
            unsigned Af[4][4];
#pragma unroll
            for (int m = 0; m < 4; m++) LDSM_X4(Af[m], aH[b] + aoffA[m] + kOff);
#pragma unroll
            for (int j = 0; j < 2; j++) {
                unsigned BH[4], BL[4];
                LDSM_X4(BH, aH[b] + boffB[j] + kOff);
                LDSM_X4(BL, aL[b] + boffB[j] + kOff);
                unsigned B0h[2] = {BH[0], BH[1]}, B1h[2] = {BH[2], BH[3]};
                unsigned B0l[2] = {BL[0], BL[1]}, B1l[2] = {BL[2], BL[3]};
#pragma unroll
                for (int m = 0; m < 4; m++) {
                    mmah(acc[m][2 * j],     Af[m], B0h);
                    mmah(acc[m][2 * j],     Af[m], B0l);
                    mmah(acc[m][2 * j + 1], Af[m], B1h);
                    mmah(acc[m][2 * j + 1], Af[m], B1l);
                }
            }
        }

        if (ch < 15) {
            unsigned hu[8], lu[8];
#pragma unroll
            for (int q = 0; q < 4; q++) {
                split2s2(nv[q].x, nv[q].y, hu[2 * q], lu[2 * q]);
                split2s2(nv[q].z, nv[q].w, hu[2 * q + 1], lu[2 * q + 1]);
                mysum += nv[q].x + nv[q].y + nv[q].z + nv[q].w;
            }
            *(uint4*)&sH[b ^ 1][sbase]     = make_uint4(hu[0], hu[1], hu[2], hu[3]);
            *(uint4*)&sH[b ^ 1][sbase + 4] = make_uint4(hu[4], hu[5], hu[6], hu[7]);
            *(uint4*)&sL[b ^ 1][sbase]     = make_uint4(lu[0], lu[1], lu[2], lu[3]);
            *(uint4*)&sL[b ^ 1][sbase + 4] = make_uint4(lu[4], lu[5], lu[6], lu[7]);
        }
        __syncthreads();
    }

    sred[t] = mysum;
    __syncthreads();
    if (t < 128)
        g_spart[(bb * KSPLIT + kc) * CI + t] = sred[2 * t] + sred[2 * t + 1];

    float* P = g_Gpart + ((size_t)(bb * KSPLIT + kc)) * CI * CI;
#pragma unroll
    for (int m = 0; m < 4; m++) {
        const int r0 = wr + m * 16 + qr;
#pragma unroll
        for (int n = 0; n < 4; n++) {
            const int c0 = wc + n * 8 + qc * 2;
            *(float2*)(P + (size_t)r0 * CI + c0)       = make_float2(acc[m][n][0], acc[m][n][1]);
            *(float2*)(P + (size_t)(r0 + 8) * CI + c0) = make_float2(acc[m][n][2], acc[m][n][3]);
        }
    }
}

// =====================================================================
// Kernel 2: chain, tensorized (round-10/11 proven, unchanged).
// =====================================================================
#define CH_PK   (128 * APR * 4)
#define CH_OF32 (4 * CH_PK)
#define CH_SMEM (CH_OF32 + 128 * F32S * 4)

__device__ __forceinline__ void mgh3(const unsigned* __restrict__ Ah,
                                     const unsigned* __restrict__ Al,
                                     const unsigned* __restrict__ Bh,
                                     const unsigned* __restrict__ Bl,
                                     float* __restrict__ O, int t)
{
    const int lane = t & 31, w = t >> 5;
    const int wr = (w >> 2) * 64, wc = (w & 3) * 32;
    const int qr = lane >> 2, qc = lane & 3;
    float acc[4][4][4];
#pragma unroll
    for (int m = 0; m < 4; m++)
#pragma unroll
        for (int n = 0; n < 4; n++)
#pragma unroll
            for (int r = 0; r < 4; r++) acc[m][n][r] = 0.f;

#pragma unroll
    for (int s = 0; s < 8; s++) {
        const int kp = s * 8;
        unsigned Afh[4][4], Afl[4][4];
#pragma unroll
        for (int m = 0; m < 4; m++) {
            const int ar = wr + m * 16 + qr;
            Afh[m][0] = Ah[ar * APR + kp + qc];
            Afh[m][1] = Ah[(ar + 8) * APR + kp + qc];
            Afh[m][2] = Ah[ar * APR + kp + qc + 4];
            Afh[m][3] = Ah[(ar + 8) * APR + kp + qc + 4];
            Afl[m][0] = Al[ar * APR + kp + qc];
            Afl[m][1] = Al[(ar + 8) * APR + kp + qc];
            Afl[m][2] = Al[ar * APR + kp + qc + 4];
            Afl[m][3] = Al[(ar + 8) * APR + kp + qc + 4];
        }
#pragma unroll
        for (int n = 0; n < 4; n++) {
            const int br = wc + n * 8 + qr;
            unsigned Bfh[2] = {Bh[br * APR + kp + qc], Bh[br * APR + kp + qc + 4]};
            unsigned Bfl[2] = {Bl[br * APR + kp + qc], Bl[br * APR + kp + qc + 4]};
#pragma unroll
            for (int m = 0; m < 4; m++) {
                mmah(acc[m][n], Afh[m], Bfh);
                mmah(acc[m][n], Afh[m], Bfl);
                mmah(acc[m][n], Afl[m], Bfh);
            }
        }
    }
#pragma unroll
    for (int m = 0; m < 4; m++) {
        const int r0 = wr + m * 16 + qr;
#pragma unroll
        for (int n = 0; n < 4; n++) {
            const int c0 = wc + n * 8 + qc * 2;
            *(float2*)&O[r0 * F32S + c0]       = make_float2(acc[m][n][0], acc[m][n][1]);
            *(float2*)&O[(r0 + 8) * F32S + c0] = make_float2(acc[m][n][2], acc[m][n][3]);
        }
    }
}

__device__ __forceinline__ void mgh3_final(const unsigned* __restrict__ Ah,
                                           const unsigned* __restrict__ Al,
                                           const unsigned* __restrict__ Bh,
                                           const unsigned* __restrict__ Bl,
                                           unsigned* __restrict__ gAh,
                                           unsigned* __restrict__ gAl,
                                           const float* __restrict__ scale, int t)
{
    const int lane = t & 31, w = t >> 5;
    const int wr = (w >> 2) * 64, wc = (w & 3) * 32;
    const int qr = lane >> 2, qc = lane & 3;
    float acc[4][4][4];
#pragma unroll
    for (int m = 0; m < 4; m++)
#pragma unroll
        for (int n = 0; n < 4; n++)
#pragma unroll
            for (int r = 0; r < 4; r++) acc[m][n][r] = 0.f;

#pragma unroll
    for (int s = 0; s < 8; s++) {
        const int kp = s * 8;
        unsigned Afh[4][4], Afl[4][4];
#pragma unroll
        for (int m = 0; m < 4; m++) {
            const int ar = wr + m * 16 + qr;
            Afh[m][0] = Ah[ar * APR + kp + qc];
            Afh[m][1] = Ah[(ar + 8) * APR + kp + qc];
            Afh[m][2] = Ah[ar * APR + kp + qc + 4];
            Afh[m][3] = Ah[(ar + 8) * APR + kp + qc + 4];
            Afl[m][0] = Al[ar * APR + kp + qc];
            Afl[m][1] = Al[(ar + 8) * APR + kp + qc];
            Afl[m][2] = Al[ar * APR + kp + qc + 4];
            Afl[m][3] = Al[(ar + 8) * APR + kp + qc + 4];
        }
#pragma unroll
        for (int n = 0; n < 4; n++) {
            const int br = wc + n * 8 + qr;
            unsigned Bfh[2] = {Bh[br * APR + kp + qc], Bh[br * APR + kp + qc + 4]};
            unsigned Bfl[2] = {Bl[br * APR + kp + qc], Bl[br * APR + kp + qc + 4]};
#pragma unroll
            for (int m = 0; m < 4; m++) {
                mmah(acc[m][n], Afh[m], Bfh);
                mmah(acc[m][n], Afh[m], Bfl);
                mmah(acc[m][n], Afl[m], Bfh);
            }
        }
    }
#pragma unroll
    for (int m = 0; m < 4; m++) {
        const int r0 = wr + m * 16 + qr;
        const float s0 = scale[r0], s1 = scale[r0 + 8];
#pragma unroll
        for (int n = 0; n < 4; n++) {
            const int c0 = wc + n * 8 + qc * 2;
            float v0 = s0 * acc[m][n][0] + ((r0 == c0) ? 1.f : 0.f);
            float v1 = s0 * acc[m][n][1] + ((r0 == c0 + 1) ? 1.f : 0.f);
            float v2 = s1 * acc[m][n][2] + ((r0 + 8 == c0) ? 1.f : 0.f);
            float v3 = s1 * acc[m][n][3] + ((r0 + 8 == c0 + 1) ? 1.f : 0.f);
            unsigned hu, lu;
            split2(v0, v1, hu, lu);
            gAh[r0 * 64 + c0 / 2] = hu;
            gAl[r0 * 64 + c0 / 2] = lu;
            split2(v2, v3, hu, lu);
            gAh[(r0 + 8) * 64 + c0 / 2] = hu;
            gAl[(r0 + 8) * 64 + c0 / 2] = lu;
        }
    }
}

__device__ __forceinline__ void stage_pack_gmem(const float* __restrict__ src,
                                                unsigned* __restrict__ Ph,
                                                unsigned* __restrict__ Pl, int t)
{
    const int row = t >> 1, seg = (t & 1) * 64;
    const int base = row * APR + seg / 2;
    const float4* s4 = (const float4*)(src + row * CI + seg);
#pragma unroll
    for (int j = 0; j < 16; j++) {
        float4 v = s4[j];
        unsigned h0, l0, h1, l1;
        split2(v.x, v.y, h0, l0);
        split2(v.z, v.w, h1, l1);
        *(uint2*)&Ph[base + 2 * j] = make_uint2(h0, h1);
        *(uint2*)&Pl[base + 2 * j] = make_uint2(l0, l1);
    }
}

__device__ __forceinline__ void pack_from_smem(const float* __restrict__ F,
                                               unsigned* __restrict__ Ph,
                                               unsigned* __restrict__ Pl, int t)
{
    const int row = t >> 1, seg = (t & 1) * 64;
    const int base = row * APR + seg / 2;
    const float* fr = F + row * F32S + seg;
#pragma unroll
    for (int j = 0; j < 32; j++) {
        float2 v = *(const float2*)(fr + 2 * j);
        unsigned h, l;
        split2(v.x, v.y, h, l);
        Ph[base + j] = h;
        Pl[base + j] = l;
    }
}

__device__ __forceinline__ float dot_packed(const unsigned* __restrict__ Ph,
                                            const unsigned* __restrict__ Pl,
                                            int row, const float* __restrict__ s)
{
    float acc = 0.f;
#pragma unroll 8
    for (int p = 0; p < 64; p++) {
        float2 hf = __half22float2(*(const __half2*)&Ph[row * APR + p]);
        float2 lf = __half22float2(*(const __half2*)&Pl[row * APR + p]);
        acc += (hf.x + lf.x) * s[2 * p] + (hf.y + lf.y) * s[2 * p + 1];
    }
    return acc;
}

__global__ void __launch_bounds__(256)
chain_kernel(const float* __restrict__ theta_w, const float* __restrict__ theta_b,
             const float* __restrict__ phi_w,   const float* __restrict__ phi_b,
             const float* __restrict__ g_w,     const float* __restrict__ g_b,
             const float* __restrict__ W_w,     const float* __restrict__ W_b,
             const float* __restrict__ bn_gamma, const float* __restrict__ bn_beta,
             const float* __restrict__ bn_mean,  const float* __restrict__ bn_var)
{
    extern __shared__ char csm[];
    unsigned* P0h = (unsigned*)(csm);
    unsigned* P0l = (unsigned*)(csm + CH_PK);
    unsigned* P1h = (unsigned*)(csm + 2 * CH_PK);
    unsigned* P1l = (unsigned*)(csm + 3 * CH_PK);
    float*    F32 = (float*)(csm + CH_OF32);

    __shared__ float sv_s[CI], sv_u[CI], sv_q[CI], sv_tb[CI],
                     sv_gb[CI], sv_c[CI], sv_scale[CI];

    const int t  = threadIdx.x;
    const int bb = blockIdx.x;

    const float* Gp = g_Gpart + (size_t)bb * KSPLIT * CI * CI;
    for (int idx = t; idx < CI * CI; idx += 256) {
        float v = 0.f;
#pragma unroll
        for (int ks = 0; ks < KSPLIT; ks++) v += Gp[ks * CI * CI + idx];
        F32[(idx >> 7) * F32S + (idx & 127)] = v;
    }
    if (t < CI) {
        float v = 0.f;
#pragma unroll
        for (int ks = 0; ks < KSPLIT; ks++) v += g_spart[(bb * KSPLIT + ks) * CI + t];
        sv_s[t]  = v;
        sv_tb[t] = theta_b[t];
        sv_gb[t] = g_b[t];
        sv_scale[t] = bn_gamma[t] * rsqrtf(bn_var[t] + 1e-5f);
    }
    stage_pack_gmem(theta_w, P1h, P1l, t);
    __syncthreads();

    for (int i = t; i < 8256; i += 256) {
        int r = (int)((sqrtf(8.0f * (float)i + 1.0f) - 1.0f) * 0.5f);
        if ((r + 1) * (r + 2) / 2 <= i) r++;
        if (r * (r + 1) / 2 > i) r--;
        int c = i - r * (r + 1) / 2;
        float a = F32[r * F32S + c], b = F32[c * F32S + r];
        float g = 0.5f * (a + b);
        F32[r * F32S + c] = g;
        F32[c * F32S + r] = g;
    }
    if (t < CI)
        sv_q[t] = dot_packed(P1h, P1l, t, sv_s) + 4096.0f * sv_tb[t];
    __syncthreads();

    pack_from_smem(F32, P0h, P0l, t);
    __syncthreads();

    mgh3(P1h, P1l, P0h, P0l, F32, t);
    __syncthreads();

    pack_from_smem(F32, P0h, P0l, t);
    stage_pack_gmem(phi_w, P1h, P1l, t);
    __syncthreads();
    if (t < CI)
        sv_u[t] = dot_packed(P1h, P1l, t, sv_s);
    __syncthreads();

    mgh3(P1h, P1l, P0h, P0l, F32, t);
    __syncthreads();

    if (t < CI) {
        const float w1 = sv_u[t];
        const float w2 = phi_b[t];
        float* rowp = F32 + t * F32S;
        float mx = -1e30f;
#pragma unroll 8
        for (int d = 0; d < 128; d++) {
            float v = rowp[d] + w1 * sv_tb[d] + w2 * sv_q[d];
            rowp[d] = v;
            mx = fmaxf(mx, v);
        }
        float ssum = 0.f;
#pragma unroll 8
        for (int d = 0; d < 128; d++) {
            float ev = expf(rowp[d] - mx);
            rowp[d] = ev;
            ssum += ev;
        }
        const float inv = 1.0f / ssum;
        float cacc = 0.f;
#pragma unroll
        for (int p = 0; p < 64; p++) {
            float f0 = rowp[2 * p] * inv;
            float f1 = rowp[2 * p + 1] * inv;
            cacc += f0 * sv_gb[2 * p] + f1 * sv_gb[2 * p + 1];
            unsigned h, l;
            split2(f0, f1, h, l);
            P1h[t * APR + p] = h;
            P1l[t * APR + p] = l;
        }
        sv_c[t] = cacc;
    }
    __syncthreads();

    for (int idx = t; idx < CI * CI; idx += 256)
        F32[(idx >> 7) * F32S + (idx & 127)] = g_w[idx];
    __syncthreads();
    {
        const int k = t >> 1, d0 = (t & 1) * 64;
        const int base = k * APR + d0 / 2;
#pragma unroll
        for (int p = 0; p < 32; p++) {
            const int d = d0 + 2 * p;
            unsigned h, l;
            split2(F32[d * F32S + k], F32[(d + 1) * F32S + k], h, l);
            P0h[base + p] = h;
            P0l[base + p] = l;
        }
    }
    __syncthreads();

    mgh3(P0h, P0l, P1h, P1l, F32, t);
    __syncthreads();

    pack_from_smem(F32, P0h, P0l, t);
    stage_pack_gmem(W_w, P1h, P1l, t);
    __syncthreads();
    if (t < CI) {
        float b0 = dot_packed(P1h, P1l, t, sv_c);
        float sc = sv_scale[t];
        g_bvec[bb * CI + t] = sc * (b0 + W_b[t]) + bn_beta[t] - bn_mean[t] * sc;
    }

    mgh3_final(P1h, P1l, P0h, P0l,
               g_Ah2 + (size_t)bb * CI * 64, g_Al2 + (size_t)bb * CI * 64,
               sv_scale, t);
}

// =====================================================================
// Kernel 3: Z ~= (Ah+Al) Xh + b'  (2-product; drops A·Xl, err ~2.5e-4).
// 256 threads, 2 CTAs/SM, grid (32, 64), CTA tile 128ch x 128px.
// A'' resident; X: 4 chunks of [32 ch x 128 px] fp16-hi only,
// double-buffered. Warp grid 4x2, warp tile 32ch x 64px.
// =====================================================================
#define AP_SMEM ((2 * 128 * APR + 2 * 32 * APR) * 4)   // 87040 B

__global__ void __launch_bounds__(256, 2)
apply_kernel(const float* __restrict__ X, float* __restrict__ Z)
{
    extern __shared__ unsigned apsm[];
    unsigned* sAh = apsm;                        // [128][APR]
    unsigned* sAl = sAh + 128 * APR;
    unsigned* sXh[2] = {sAl + 128 * APR, sAl + 128 * APR + 32 * APR};

    const int t = threadIdx.x;
    const int lane = t & 31, w = t >> 5;
    const int wr = (w >> 1) * 32;          // 4 ch-groups of 32
    const int wc = (w & 1) * 64;           // 2 px-groups of 64
    const int qr = lane >> 2, qc = lane & 3;
    const int bb = blockIdx.y;
    const int px0 = blockIdx.x * 128;

    const uint32_t aAh = s2u(sAh), aAl = s2u(sAl);
    const uint32_t aXh[2] = {s2u(sXh[0]), s2u(sXh[1])};

    // ldmatrix offsets
    uint32_t aoffA[2][2];    // [m][ks]; add g*64 bytes per chunk
#pragma unroll
    for (int m = 0; m < 2; m++)
#pragma unroll
        for (int ks = 0; ks < 2; ks++)
            aoffA[m][ks] = (uint32_t)((wr + m * 16 + (lane & 15)) * APR + ks * 8) * 4u
                         + (uint32_t)((lane >> 4) & 1) * 16u;
    uint32_t boffB[2][4];    // [ks][j]  (round-12-proven trans pattern, APR stride)
#pragma unroll
    for (int ks = 0; ks < 2; ks++)
#pragma unroll
        for (int j = 0; j < 4; j++)
            boffB[ks][j] = (uint32_t)((ks * 16 + (lane & 7) + ((lane >> 3) & 1) * 8) * APR) * 4u
                         + (uint32_t)(wc + j * 16 + ((lane >> 4) & 1) * 8) * 2u;

    // ---- stage A'' hi/lo resident ONCE ----
    {
        const int row = t >> 1, seg = (t & 1) * 32;
        const uint4* Ah = (const uint4*)(g_Ah2 + ((size_t)bb * CI + row) * 64 + seg);
        const uint4* Al = (const uint4*)(g_Al2 + ((size_t)bb * CI + row) * 64 + seg);
#pragma unroll
        for (int j = 0; j < 8; j++) {
            *(uint4*)&sAh[row * APR + seg + 4 * j] = Ah[j];
            *(uint4*)&sAl[row * APR + seg + 4 * j] = Al[j];
        }
    }

    float bias[2][2];
#pragma unroll
    for (int m = 0; m < 2; m++) {
        bias[m][0] = g_bvec[bb * CI + wr + m * 16 + qr];
        bias[m][1] = g_bvec[bb * CI + wr + m * 16 + qr + 8];
    }

    const float* Xb = X + (size_t)bb * CI * NPIX;
    float* Zb = Z + (size_t)bb * CI * NPIX;

    // X loader: thread t -> chunk-row rr = t>>3 (0..31), px (t&7)*16
    const int rr = t >> 3, lpx = (t & 7) * 16;
    const int xsb = rr * APR + (t & 7) * 8;

    float acc[2][8][4];
#pragma unroll
    for (int m = 0; m < 2; m++)
#pragma unroll
        for (int n = 0; n < 8; n++)
#pragma unroll
            for (int r = 0; r < 4; r++) acc[m][n][r] = 0.f;

    // preload chunk 0 (channels 0..31), hi-parts only
    {
        const float* src = Xb + (size_t)rr * NPIX + px0 + lpx;
        unsigned hu[8];
#pragma unroll
        for (int q = 0; q < 4; q++) {
            float4 v = *(const float4*)(src + 4 * q);
            hu[2 * q]     = cvt2(v.x, v.y);
            hu[2 * q + 1] = cvt2(v.z, v.w);
        }
        *(uint4*)&sXh[0][xsb]     = make_uint4(hu[0], hu[1], hu[2], hu[3]);
        *(uint4*)&sXh[0][xsb + 4] = make_uint4(hu[4], hu[5], hu[6], hu[7]);
    }
    __syncthreads();

    // 4 k-chunks of 32 channels
    for (int g = 0; g < 4; g++) {
        const int b = g & 1;
        float4 nv[4];
        if (g < 3) {
            const float* src = Xb + (size_t)((g + 1) * 32 + rr) * NPIX + px0 + lpx;
#pragma unroll
            for (int q = 0; q < 4; q++) nv[q] = *(const float4*)(src + 4 * q);
        }

        const uint32_t gOff = (uint32_t)g * 64u;   // 32 k = 16 pairs = 64 bytes
#pragma unroll
        for (int ks = 0; ks < 2; ks++) {
            unsigned Ahf[2][4], Alf[2][4];
#pragma unroll
            for (int m = 0; m < 2; m++) {
                LDSM_X4(Ahf[m], aAh + aoffA[m][ks] + gOff);
                LDSM_X4(Alf[m], aAl + aoffA[m][ks] + gOff);
            }
#pragma unroll
            for (int j = 0; j < 4; j++) {
                unsigned BH[4];
                LDSM_X4T(BH, aXh[b] + boffB[ks][j]);
                unsigned B0h[2] = {BH[0], BH[1]}, B1h[2] = {BH[2], BH[3]};
#pragma unroll
                for (int m = 0; m < 2; m++) {
                    mmah(acc[m][2 * j],     Ahf[m], B0h);
                    mmah(acc[m][2 * j],     Alf[m], B0h);
                    mmah(acc[m][2 * j + 1], Ahf[m], B1h);
                    mmah(acc[m][2 * j + 1], Alf[m], B1h);
                }
            }
        }

        if (g < 3) {
            unsigned hu[8];
#pragma unroll
            for (int q = 0; q < 4; q++) {
                hu[2 * q]     = cvt2(nv[q].x, nv[q].y);
                hu[2 * q + 1] = cvt2(nv[q].z, nv[q].w);
            }
            *(uint4*)&sXh[b ^ 1][xsb]     = make_uint4(hu[0], hu[1], hu[2], hu[3]);
            *(uint4*)&sXh[b ^ 1][xsb + 4] = make_uint4(hu[4], hu[5], hu[6], hu[7]);
        }
        __syncthreads();
    }

    // ---- epilogue: bias + store ----
#pragma unroll
    for (int m = 0; m < 2; m++) {
        const int r0 = wr + m * 16 + qr;
#pragma unroll
        for (int n = 0; n < 8; n++) {
            const int c0 = px0 + wc + n * 8 + qc * 2;
            *(float2*)(Zb + (size_t)r0 * NPIX + c0) =
                make_float2(acc[m][n][0] + bias[m][0], acc[m][n][1] + bias[m][0]);
            *(float2*)(Zb + (size_t)(r0 + 8) * NPIX + c0) =
                make_float2(acc[m][n][2] + bias[m][1], acc[m][n][3] + bias[m][1]);
        }
    }
}

// =====================================================================
extern "C" void kernel_launch(void* const* d_in, const int* in_sizes, int n_in,
                              void* d_out, int out_size)
{
    (void)in_sizes; (void)n_in; (void)out_size;
    const float* x        = (const float*)d_in[0];
    const float* theta_w  = (const float*)d_in[1];
    const float* theta_b  = (const float*)d_in[2];
    const float* phi_w    = (const float*)d_in[3];
    const float* phi_b    = (const float*)d_in[4];
    const float* g_w      = (const float*)d_in[5];
    const float* g_b      = (const float*)d_in[6];
    const float* W_w      = (const float*)d_in[7];
    const float* W_b      = (const float*)d_in[8];
    const float* bn_gamma = (const float*)d_in[9];
    const float* bn_beta  = (const float*)d_in[10];
    const float* bn_mean  = (const float*)d_in[11];
    const float* bn_var   = (const float*)d_in[12];
    float* out = (float*)d_out;

    cudaFuncSetAttribute(chain_kernel,
                         cudaFuncAttributeMaxDynamicSharedMemorySize, CH_SMEM);
    cudaFuncSetAttribute(apply_kernel,
                         cudaFuncAttributeMaxDynamicSharedMemorySize, AP_SMEM);

    gram_kernel<<<dim3(KSPLIT, NB), 256>>>(x);
    chain_kernel<<<NB, 256, CH_SMEM>>>(theta_w, theta_b, phi_w, phi_b,
                                       g_w, g_b, W_w, W_b,
                                       bn_gamma, bn_beta, bn_mean, bn_var);
    apply_kernel<<<dim3(NPIX / 128, NB), 256, AP_SMEM>>>(x, out);
}

// round 15
// speedup vs baseline: 1.4335x; 1.1290x over previous
#include <cuda_runtime.h>
#include <cuda_fp16.h>
#include <cstdint>
#include <math.h>

// Problem constants:
//  x: [16, 512, 64, 64] fp32 == [64 batches][128 ch][4096 px] contiguous
#define NB     64
#define CI     128
#define NPIX   4096
#define KSPLIT 8                 // gram K-split CTAs per batch (K=512 each)
#define GP2    20                // gram pair stride (16 pairs + 4) [80B, ldsm-cf]
#define APR    68                // packed pair stride (64 pairs + 4) [272B, ldsm-cf]
#define F32S   132               // chain fp32 scratch stride

// ---------------- fp16 helpers ----------------
__device__ __forceinline__ void split2(float a, float b, unsigned& hu, unsigned& lu) {
    __half2 h2 = __float22half2_rn(make_float2(a, b));
    float2 hf = __half22float2(h2);
    __half2 l2 = __float22half2_rn(make_float2(a - hf.x, b - hf.y));
    hu = *(unsigned*)&h2;
    lu = *(unsigned*)&l2;
}
__device__ __forceinline__ void split2s2(float a, float b, unsigned& hu, unsigned& lu) {
    __half2 h2 = __float22half2_rn(make_float2(a, b));
    float2 hf = __half22float2(h2);
    __half2 l2 = __float22half2_rn(make_float2((a - hf.x) * 2.0f, (b - hf.y) * 2.0f));
    hu = *(unsigned*)&h2;
    lu = *(unsigned*)&l2;
}
__device__ __forceinline__ unsigned cvt2(float a, float b) {
    __half2 h2 = __float22half2_rn(make_float2(a, b));
    return *(unsigned*)&h2;
}

// D += A(16x16,row,f16) * B(16x8,col,f16)  fp32-accum
__device__ __forceinline__ void mmah(float* d, const unsigned* a, const unsigned* b) {
    asm volatile(
        "mma.sync.aligned.m16n8k16.row.col.f32.f16.f16.f32 "
        "{%0,%1,%2,%3}, {%4,%5,%6,%7}, {%8,%9}, {%0,%1,%2,%3};"
        : "+f"(d[0]), "+f"(d[1]), "+f"(d[2]), "+f"(d[3])
        : "r"(a[0]), "r"(a[1]), "r"(a[2]), "r"(a[3]), "r"(b[0]), "r"(b[1]));
}

__device__ __forceinline__ uint32_t s2u(const void* p) {
    return (uint32_t)__cvta_generic_to_shared(p);
}
#define LDSM_X4(r, addr) \
    asm volatile("ldmatrix.sync.aligned.m8n8.x4.shared.b16 {%0,%1,%2,%3}, [%4];" \
        : "=r"((r)[0]), "=r"((r)[1]), "=r"((r)[2]), "=r"((r)[3]) : "r"(addr))
#define LDSM_X4T(r, addr) \
    asm volatile("ldmatrix.sync.aligned.m8n8.x4.trans.shared.b16 {%0,%1,%2,%3}, [%4];" \
        : "=r"((r)[0]), "=r"((r)[1]), "=r"((r)[2]), "=r"((r)[3]) : "r"(addr))

// ---------------- scratch ----------------
__device__ float    g_Gpart[NB * KSPLIT * CI * CI]; // partial E (G = (E+E^T)/2)
__device__ float    g_spart[NB * KSPLIT * CI];      // partial row sums
__device__ unsigned g_Ah2[NB * CI * 64];            // A'' fp16-hi, half2 pairs
__device__ unsigned g_Al2[NB * CI * 64];            // A'' fp16-lo, half2 pairs
__device__ float    g_bvec[NB * CI];                // folded bias b'

// =====================================================================
// Kernel 1 (round-14 proven, 65.7us): partial E = H H^T + H (2L)^T.
// 32-px chunks, grid (KSPLIT, NB), 256 threads, 2 CTAs/SM.
// =====================================================================
__global__ void __launch_bounds__(256, 2)
gram_kernel(const float* __restrict__ X)
{
    __shared__ unsigned sH[2][128 * GP2];
    __shared__ unsigned sL[2][128 * GP2];
    __shared__ float sred[256];

    const int t = threadIdx.x;
    const int lane = t & 31, w = t >> 5;
    const int wr = (w >> 2) * 64, wc = (w & 3) * 32;
    const int qr = lane >> 2, qc = lane & 3;
    const int kc = blockIdx.x, bb = blockIdx.y;

    const float* Xb = X + (size_t)bb * CI * NPIX + (size_t)kc * 512;
    const int lrow = t >> 1;
    const int sbase = lrow * GP2 + (t & 1) * 8;
    const float* Xr = Xb + (size_t)lrow * NPIX + (t & 1) * 16;

    const uint32_t aH[2] = {s2u(sH[0]), s2u(sH[1])};
    const uint32_t aL[2] = {s2u(sL[0]), s2u(sL[1])};

    uint32_t aoffA[4], boffB[2];
#pragma unroll
    for (int m = 0; m < 4; m++)
        aoffA[m] = (uint32_t)((wr + m * 16 + (lane & 15)) * GP2) * 4u
                 + (uint32_t)((lane >> 4) & 1) * 16u;
#pragma unroll
    for (int j = 0; j < 2; j++)
        boffB[j] = (uint32_t)((wc + j * 16 + (lane & 7) + ((lane >> 4) & 1) * 8) * GP2) * 4u
                 + (uint32_t)((lane >> 3) & 1) * 16u;

    float acc[4][4][4];
#pragma unroll
    for (int m = 0; m < 4; m++)
#pragma unroll
        for (int n = 0; n < 4; n++)
#pragma unroll
            for (int r = 0; r < 4; r++) acc[m][n][r] = 0.f;
    float mysum = 0.f;

    {
        float4 v[4];
#pragma unroll
        for (int q = 0; q < 4; q++) v[q] = *(const float4*)(Xr + 4 * q);
        unsigned hu[8], lu[8];
#pragma unroll
        for (int q = 0; q < 4; q++) {
            split2s2(v[q].x, v[q].y, hu[2 * q], lu[2 * q]);
            split2s2(v[q].z, v[q].w, hu[2 * q + 1], lu[2 * q + 1]);
            mysum += v[q].x + v[q].y + v[q].z + v[q].w;
        }
        *(uint4*)&sH[0][sbase]     = make_uint4(hu[0], hu[1], hu[2], hu[3]);
        *(uint4*)&sH[0][sbase + 4] = make_uint4(hu[4], hu[5], hu[6], hu[7]);
        *(uint4*)&sL[0][sbase]     = make_uint4(lu[0], lu[1], lu[2], lu[3]);
        *(uint4*)&sL[0][sbase + 4] = make_uint4(lu[4], lu[5], lu[6], lu[7]);
    }
    __syncthreads();

    for (int ch = 0; ch < 16; ch++) {
        const int b = ch & 1;
        float4 nv[4];
        if (ch < 15) {
#pragma unroll
            for (int q = 0; q < 4; q++)
                nv[q] = *(const float4*)(Xr + (ch + 1) * 32 + 4 * q);
        }

#pragma unroll
        for (int ks = 0; ks < 2; ks++) {
            const uint32_t kOff = (uint32_t)ks * 32u;
            unsigned Af[4][4];
#pragma unroll
            for (int m = 0; m < 4; m++) LDSM_X4(Af[m], aH[b] + aoffA[m] + kOff);
#pragma unroll
            for (int j = 0; j < 2; j++) {
                unsigned BH[4], BL[4];
                LDSM_X4(BH, aH[b] + boffB[j] + kOff);
                LDSM_X4(BL, aL[b] + boffB[j] + kOff);
                unsigned B0h[2] = {BH[0], BH[1]}, B1h[2] = {BH[2], BH[3]};
                unsigned B0l[2] = {BL[0], BL[1]}, B1l[2] = {BL[2], BL[3]};
#pragma unroll
                for (int m = 0; m < 4; m++) {
                    mmah(acc[m][2 * j],     Af[m], B0h);
                    mmah(acc[m][2 * j],     Af[m], B0l);
                    mmah(acc[m][2 * j + 1], Af[m], B1h);
                    mmah(acc[m][2 * j + 1], Af[m], B1l);
                }
            }
        }

        if (ch < 15) {
            unsigned hu[8], lu[8];
#pragma unroll
            for (int q = 0; q < 4; q++) {
                split2s2(nv[q].x, nv[q].y, hu[2 * q], lu[2 * q]);
                split2s2(nv[q].z, nv[q].w, hu[2 * q + 1], lu[2 * q + 1]);
                mysum += nv[q].x + nv[q].y + nv[q].z + nv[q].w;
            }
            *(uint4*)&sH[b ^ 1][sbase]     = make_uint4(hu[0], hu[1], hu[2], hu[3]);
            *(uint4*)&sH[b ^ 1][sbase + 4] = make_uint4(hu[4], hu[5], hu[6], hu[7]);
            *(uint4*)&sL[b ^ 1][sbase]     = make_uint4(lu[0], lu[1], lu[2], lu[3]);
            *(uint4*)&sL[b ^ 1][sbase + 4] = make_uint4(lu[4], lu[5], lu[6], lu[7]);
        }
        __syncthreads();
    }

    sred[t] = mysum;
    __syncthreads();
    if (t < 128)
        g_spart[(bb * KSPLIT + kc) * CI + t] = sred[2 * t] + sred[2 * t + 1];

    float* P = g_Gpart + ((size_t)(bb * KSPLIT + kc)) * CI * CI;
#pragma unroll
    for (int m = 0; m < 4; m++) {
        const int r0 = wr + m * 16 + qr;
#pragma unroll
        for (int n = 0; n < 4; n++) {
            const int c0 = wc + n * 8 + qc * 2;
            *(float2*)(P + (size_t)r0 * CI + c0)       = make_float2(acc[m][n][0], acc[m][n][1]);
            *(float2*)(P + (size_t)(r0 + 8) * CI + c0) = make_float2(acc[m][n][2], acc[m][n][3]);
        }
    }
}

// =====================================================================
// Kernel 2: chain, tensorized (round-10/11 proven, unchanged).
// =====================================================================
#define CH_PK   (128 * APR * 4)
#define CH_OF32 (4 * CH_PK)
#define CH_SMEM (CH_OF32 + 128 * F32S * 4)

__device__ __forceinline__ void mgh3(const unsigned* __restrict__ Ah,
                                     const unsigned* __restrict__ Al,
                                     const unsigned* __restrict__ Bh,
                                     const unsigned* __restrict__ Bl,
                                     float* __restrict__ O, int t)
{
    const int lane = t & 31, w = t >> 5;
    const int wr = (w >> 2) * 64, wc = (w & 3) * 32;
    const int qr = lane >> 2, qc = lane & 3;
    float acc[4][4][4];
#pragma unroll
    for (int m = 0; m < 4; m++)
#pragma unroll
        for (int n = 0; n < 4; n++)
#pragma unroll
            for (int r = 0; r < 4; r++) acc[m][n][r] = 0.f;

#pragma unroll
    for (int s = 0; s < 8; s++) {
        const int kp = s * 8;
        unsigned Afh[4][4], Afl[4][4];
#pragma unroll
        for (int m = 0; m < 4; m++) {
            const int ar = wr + m * 16 + qr;
            Afh[m][0] = Ah[ar * APR + kp + qc];
            Afh[m][1] = Ah[(ar + 8) * APR + kp + qc];
            Afh[m][2] = Ah[ar * APR + kp + qc + 4];
            Afh[m][3] = Ah[(ar + 8) * APR + kp + qc + 4];
            Afl[m][0] = Al[ar * APR + kp + qc];
            Afl[m][1] = Al[(ar + 8) * APR + kp + qc];
            Afl[m][2] = Al[ar * APR + kp + qc + 4];
            Afl[m][3] = Al[(ar + 8) * APR + kp + qc + 4];
        }
#pragma unroll
        for (int n = 0; n < 4; n++) {
            const int br = wc + n * 8 + qr;
            unsigned Bfh[2] = {Bh[br * APR + kp + qc], Bh[br * APR + kp + qc + 4]};
            unsigned Bfl[2] = {Bl[br * APR + kp + qc], Bl[br * APR + kp + qc + 4]};
#pragma unroll
            for (int m = 0; m < 4; m++) {
                mmah(acc[m][n], Afh[m], Bfh);
                mmah(acc[m][n], Afh[m], Bfl);
                mmah(acc[m][n], Afl[m], Bfh);
            }
        }
    }
#pragma unroll
    for (int m = 0; m < 4; m++) {
        const int r0 = wr + m * 16 + qr;
#pragma unroll
        for (int n = 0; n < 4; n++) {
            const int c0 = wc + n * 8 + qc * 2;
            *(float2*)&O[r0 * F32S + c0]       = make_float2(acc[m][n][0], acc[m][n][1]);
            *(float2*)&O[(r0 + 8) * F32S + c0] = make_float2(acc[m][n][2], acc[m][n][3]);
        }
    }
}

__device__ __forceinline__ void mgh3_final(const unsigned* __restrict__ Ah,
                                           const unsigned* __restrict__ Al,
                                           const unsigned* __restrict__ Bh,
                                           const unsigned* __restrict__ Bl,
                                           unsigned* __restrict__ gAh,
                                           unsigned* __restrict__ gAl,
                                           const float* __restrict__ scale, int t)
{
    const int lane = t & 31, w = t >> 5;
    const int wr = (w >> 2) * 64, wc = (w & 3) * 32;
    const int qr = lane >> 2, qc = lane & 3;
    float acc[4][4][4];
#pragma unroll
    for (int m = 0; m < 4; m++)
#pragma unroll
        for (int n = 0; n < 4; n++)
#pragma unroll
            for (int r = 0; r < 4; r++) acc[m][n][r] = 0.f;

#pragma unroll
    for (int s = 0; s < 8; s++) {
        const int kp = s * 8;
        unsigned Afh[4][4], Afl[4][4];
#pragma unroll
        for (int m = 0; m < 4; m++) {
            const int ar = wr + m * 16 + qr;
            Afh[m][0] = Ah[ar * APR + kp + qc];
            Afh[m][1] = Ah[(ar + 8) * APR + kp + qc];
            Afh[m][2] = Ah[ar * APR + kp + qc + 4];
            Afh[m][3] = Ah[(ar + 8) * APR + kp + qc + 4];
            Afl[m][0] = Al[ar * APR + kp + qc];
            Afl[m][1] = Al[(ar + 8) * APR + kp + qc];
            Afl[m][2] = Al[ar * APR + kp + qc + 4];
            Afl[m][3] = Al[(ar + 8) * APR + kp + qc + 4];
        }
#pragma unroll
        for (int n = 0; n < 4; n++) {
            const int br = wc + n * 8 + qr;
            unsigned Bfh[2] = {Bh[br * APR + kp + qc], Bh[br * APR + kp + qc + 4]};
            unsigned Bfl[2] = {Bl[br * APR + kp + qc], Bl[br * APR + kp + qc + 4]};
#pragma unroll
            for (int m = 0; m < 4; m++) {
                mmah(acc[m][n], Afh[m], Bfh);
                mmah(acc[m][n], Afh[m], Bfl);
                mmah(acc[m][n], Afl[m], Bfh);
            }
        }
    }
#pragma unroll
    for (int m = 0; m < 4; m++) {
        const int r0 = wr + m * 16 + qr;
        const float s0 = scale[r0], s1 = scale[r0 + 8];
#pragma unroll
        for (int n = 0; n < 4; n++) {
            const int c0 = wc + n * 8 + qc * 2;
            float v0 = s0 * acc[m][n][0] + ((r0 == c0) ? 1.f : 0.f);
            float v1 = s0 * acc[m][n][1] + ((r0 == c0 + 1) ? 1.f : 0.f);
            float v2 = s1 * acc[m][n][2] + ((r0 + 8 == c0) ? 1.f : 0.f);
            float v3 = s1 * acc[m][n][3] + ((r0 + 8 == c0 + 1) ? 1.f : 0.f);
            unsigned hu, lu;
            split2(v0, v1, hu, lu);
            gAh[r0 * 64 + c0 / 2] = hu;
            gAl[r0 * 64 + c0 / 2] = lu;
            split2(v2, v3, hu, lu);
            gAh[(r0 + 8) * 64 + c0 / 2] = hu;
            gAl[(r0 + 8) * 64 + c0 / 2] = lu;
        }
    }
}

__device__ __forceinline__ void stage_pack_gmem(const float* __restrict__ src,
                                                unsigned* __restrict__ Ph,
                                                unsigned* __restrict__ Pl, int t)
{
    const int row = t >> 1, seg = (t & 1) * 64;
    const int base = row * APR + seg / 2;
    const float4* s4 = (const float4*)(src + row * CI + seg);
#pragma unroll
    for (int j = 0; j < 16; j++) {
        float4 v = s4[j];
        unsigned h0, l0, h1, l1;
        split2(v.x, v.y, h0, l0);
        split2(v.z, v.w, h1, l1);
        *(uint2*)&Ph[base + 2 * j] = make_uint2(h0, h1);
        *(uint2*)&Pl[base + 2 * j] = make_uint2(l0, l1);
    }
}

__device__ __forceinline__ void pack_from_smem(const float* __restrict__ F,
                                               unsigned* __restrict__ Ph,
                                               unsigned* __restrict__ Pl, int t)
{
    const int row = t >> 1, seg = (t & 1) * 64;
    const int base = row * APR + seg / 2;
    const float* fr = F + row * F32S + seg;
#pragma unroll
    for (int j = 0; j < 32; j++) {
        float2 v = *(const float2*)(fr + 2 * j);
        unsigned h, l;
        split2(v.x, v.y, h, l);
        Ph[base + j] = h;
        Pl[base + j] = l;
    }
}

__device__ __forceinline__ float dot_packed(const unsigned* __restrict__ Ph,
                                            const unsigned* __restrict__ Pl,
                                            int row, const float* __restrict__ s)
{
    float acc = 0.f;
#pragma unroll 8
    for (int p = 0; p < 64; p++) {
        float2 hf = __half22float2(*(const __half2*)&Ph[row * APR + p]);
        float2 lf = __half22float2(*(const __half2*)&Pl[row * APR + p]);
        acc += (hf.x + lf.x) * s[2 * p] + (hf.y + lf.y) * s[2 * p + 1];
    }
    return acc;
}

__global__ void __launch_bounds__(256)
chain_kernel(const float* __restrict__ theta_w, const float* __restrict__ theta_b,
             const float* __restrict__ phi_w,   const float* __restrict__ phi_b,
             const float* __restrict__ g_w,     const float* __restrict__ g_b,
             const float* __restrict__ W_w,     const float* __restrict__ W_b,
             const float* __restrict__ bn_gamma, const float* __restrict__ bn_beta,
             const float* __restrict__ bn_mean,  const float* __restrict__ bn_var)
{
    extern __shared__ char csm[];
    unsigned* P0h = (unsigned*)(csm);
    unsigned* P0l = (unsigned*)(csm + CH_PK);
    unsigned* P1h = (unsigned*)(csm + 2 * CH_PK);
    unsigned* P1l = (unsigned*)(csm + 3 * CH_PK);
    float*    F32 = (float*)(csm + CH_OF32);

    __shared__ float sv_s[CI], sv_u[CI], sv_q[CI], sv_tb[CI],
                     sv_gb[CI], sv_c[CI], sv_scale[CI];

    const int t  = threadIdx.x;
    const int bb = blockIdx.x;

    const float* Gp = g_Gpart + (size_t)bb * KSPLIT * CI * CI;
    for (int idx = t; idx < CI * CI; idx += 256) {
        float v = 0.f;
#pragma unroll
        for (int ks = 0; ks < KSPLIT; ks++) v += Gp[ks * CI * CI + idx];
        F32[(idx >> 7) * F32S + (idx & 127)] = v;
    }
    if (t < CI) {
        float v = 0.f;
#pragma unroll
        for (int ks = 0; ks < KSPLIT; ks++) v += g_spart[(bb * KSPLIT + ks) * CI + t];
        sv_s[t]  = v;
        sv_tb[t] = theta_b[t];
        sv_gb[t] = g_b[t];
        sv_scale[t] = bn_gamma[t] * rsqrtf(bn_var[t] + 1e-5f);
    }
    stage_pack_gmem(theta_w, P1h, P1l, t);
    __syncthreads();

    for (int i = t; i < 8256; i += 256) {
        int r = (int)((sqrtf(8.0f * (float)i + 1.0f) - 1.0f) * 0.5f);
        if ((r + 1) * (r + 2) / 2 <= i) r++;
        if (r * (r + 1) / 2 > i) r--;
        int c = i - r * (r + 1) / 2;
        float a = F32[r * F32S + c], b = F32[c * F32S + r];
        float g = 0.5f * (a + b);
        F32[r * F32S + c] = g;
        F32[c * F32S + r] = g;
    }
    if (t < CI)
        sv_q[t] = dot_packed(P1h, P1l, t, sv_s) + 4096.0f * sv_tb[t];
    __syncthreads();

    pack_from_smem(F32, P0h, P0l, t);
    __syncthreads();

    mgh3(P1h, P1l, P0h, P0l, F32, t);
    __syncthreads();

    pack_from_smem(F32, P0h, P0l, t);
    stage_pack_gmem(phi_w, P1h, P1l, t);
    __syncthreads();
    if (t < CI)
        sv_u[t] = dot_packed(P1h, P1l, t, sv_s);
    __syncthreads();

    mgh3(P1h, P1l, P0h, P0l, F32, t);
    __syncthreads();

    if (t < CI) {
        const float w1 = sv_u[t];
        const float w2 = phi_b[t];
        float* rowp = F32 + t * F32S;
        float mx = -1e30f;
#pragma unroll 8
        for (int d = 0; d < 128; d++) {
            float v = rowp[d] + w1 * sv_tb[d] + w2 * sv_q[d];
            rowp[d] = v;
            mx = fmaxf(mx, v);
        }
        float ssum = 0.f;
#pragma unroll 8
        for (int d = 0; d < 128; d++) {
            float ev = expf(rowp[d] - mx);
            rowp[d] = ev;
            ssum += ev;
        }
        const float inv = 1.0f / ssum;
        float cacc = 0.f;
#pragma unroll
        for (int p = 0; p < 64; p++) {
            float f0 = rowp[2 * p] * inv;
            float f1 = rowp[2 * p + 1] * inv;
            cacc += f0 * sv_gb[2 * p] + f1 * sv_gb[2 * p + 1];
            unsigned h, l;
            split2(f0, f1, h, l);
            P1h[t * APR + p] = h;
            P1l[t * APR + p] = l;
        }
        sv_c[t] = cacc;
    }
    __syncthreads();

    for (int idx = t; idx < CI * CI; idx += 256)
        F32[(idx >> 7) * F32S + (idx & 127)] = g_w[idx];
    __syncthreads();
    {
        const int k = t >> 1, d0 = (t & 1) * 64;
        const int base = k * APR + d0 / 2;
#pragma unroll
        for (int p = 0; p < 32; p++) {
            const int d = d0 + 2 * p;
            unsigned h, l;
            split2(F32[d * F32S + k], F32[(d + 1) * F32S + k], h, l);
            P0h[base + p] = h;
            P0l[base + p] = l;
        }
    }
    __syncthreads();

    mgh3(P0h, P0l, P1h, P1l, F32, t);
    __syncthreads();

    pack_from_smem(F32, P0h, P0l, t);
    stage_pack_gmem(W_w, P1h, P1l, t);
    __syncthreads();
    if (t < CI) {
        float b0 = dot_packed(P1h, P1l, t, sv_c);
        float sc = sv_scale[t];
        g_bvec[bb * CI + t] = sc * (b0 + W_b[t]) + bn_beta[t] - bn_mean[t] * sc;
    }

    mgh3_final(P1h, P1l, P0h, P0l,
               g_Ah2 + (size_t)bb * CI * 64, g_Al2 + (size_t)bb * CI * 64,
               sv_scale, t);
}

// =====================================================================
// Kernel 3: Z ~= Ah Xh + b'  (pure fp16 single product).
// 256 threads, 2 CTAs/SM, grid (32, 64), CTA tile 128ch x 128px.
// Ah resident only (34.8KB); X: 4 chunks of [32 ch x 128 px] fp16-hi,
// double-buffered. Warp grid 4x2, warp tile 32ch x 64px.
// =====================================================================
#define AP_SMEM ((128 * APR + 2 * 32 * APR) * 4)   // 52224 B

__global__ void __launch_bounds__(256, 2)
apply_kernel(const float* __restrict__ X, float* __restrict__ Z)
{
    extern __shared__ unsigned apsm[];
    unsigned* sAh = apsm;                        // [128][APR]
    unsigned* sXh[2] = {sAh + 128 * APR, sAh + 128 * APR + 32 * APR};

    const int t = threadIdx.x;
    const int lane = t & 31, w = t >> 5;
    const int wr = (w >> 1) * 32;          // 4 ch-groups of 32
    const int wc = (w & 1) * 64;           // 2 px-groups of 64
    const int qr = lane >> 2, qc = lane & 3;
    const int bb = blockIdx.y;
    const int px0 = blockIdx.x * 128;

    const uint32_t aAh = s2u(sAh);
    const uint32_t aXh[2] = {s2u(sXh[0]), s2u(sXh[1])};

    uint32_t aoffA[2][2];    // [m][ks]; add g*64 bytes per chunk
#pragma unroll
    for (int m = 0; m < 2; m++)
#pragma unroll
        for (int ks = 0; ks < 2; ks++)
            aoffA[m][ks] = (uint32_t)((wr + m * 16 + (lane & 15)) * APR + ks * 8) * 4u
                         + (uint32_t)((lane >> 4) & 1) * 16u;
    uint32_t boffB[2][4];    // [ks][j]
#pragma unroll
    for (int ks = 0; ks < 2; ks++)
#pragma unroll
        for (int j = 0; j < 4; j++)
            boffB[ks][j] = (uint32_t)((ks * 16 + (lane & 7) + ((lane >> 3) & 1) * 8) * APR) * 4u
                         + (uint32_t)(wc + j * 16 + ((lane >> 4) & 1) * 8) * 2u;

    // ---- stage A'' hi resident ONCE ----
    {
        const int row = t >> 1, seg = (t & 1) * 32;
        const uint4* Ah = (const uint4*)(g_Ah2 + ((size_t)bb * CI + row) * 64 + seg);
#pragma unroll
        for (int j = 0; j < 8; j++)
            *(uint4*)&sAh[row * APR + seg + 4 * j] = Ah[j];
    }

    float bias[2][2];
#pragma unroll
    for (int m = 0; m < 2; m++) {
        bias[m][0] = g_bvec[bb * CI + wr + m * 16 + qr];
        bias[m][1] = g_bvec[bb * CI + wr + m * 16 + qr + 8];
    }

    const float* Xb = X + (size_t)bb * CI * NPIX;
    float* Zb = Z + (size_t)bb * CI * NPIX;

    // X loader: thread t -> chunk-row rr = t>>3 (0..31), px (t&7)*16
    const int rr = t >> 3, lpx = (t & 7) * 16;
    const int xsb = rr * APR + (t & 7) * 8;

    float acc[2][8][4];
#pragma unroll
    for (int m = 0; m < 2; m++)
#pragma unroll
        for (int n = 0; n < 8; n++)
#pragma unroll
            for (int r = 0; r < 4; r++) acc[m][n][r] = 0.f;

    // preload chunk 0 (channels 0..31), hi-parts only
    {
        const float* src = Xb + (size_t)rr * NPIX + px0 + lpx;
        unsigned hu[8];
#pragma unroll
        for (int q = 0; q < 4; q++) {
            float4 v = *(const float4*)(src + 4 * q);
            hu[2 * q]     = cvt2(v.x, v.y);
            hu[2 * q + 1] = cvt2(v.z, v.w);
        }
        *(uint4*)&sXh[0][xsb]     = make_uint4(hu[0], hu[1], hu[2], hu[3]);
        *(uint4*)&sXh[0][xsb + 4] = make_uint4(hu[4], hu[5], hu[6], hu[7]);
    }
    __syncthreads();

    // 4 k-chunks of 32 channels
    for (int g = 0; g < 4; g++) {
        const int b = g & 1;
        float4 nv[4];
        if (g < 3) {
            const float* src = Xb + (size_t)((g + 1) * 32 + rr) * NPIX + px0 + lpx;
#pragma unroll
            for (int q = 0; q < 4; q++) nv[q] = *(const float4*)(src + 4 * q);
        }

        const uint32_t gOff = (uint32_t)g * 64u;
#pragma unroll
        for (int ks = 0; ks < 2; ks++) {
            unsigned Ahf[2][4];
#pragma unroll
            for (int m = 0; m < 2; m++)
                LDSM_X4(Ahf[m], aAh + aoffA[m][ks] + gOff);
#pragma unroll
            for (int j = 0; j < 4; j++) {
                unsigned BH[4];
                LDSM_X4T(BH, aXh[b] + boffB[ks][j]);
                unsigned B0h[2] = {BH[0], BH[1]}, B1h[2] = {BH[2], BH[3]};
#pragma unroll
                for (int m = 0; m < 2; m++) {
                    mmah(acc[m][2 * j],     Ahf[m], B0h);
                    mmah(acc[m][2 * j + 1], Ahf[m], B1h);
                }
            }
        }

        if (g < 3) {
            unsigned hu[8];
#pragma unroll
            for (int q = 0; q < 4; q++) {
                hu[2 * q]     = cvt2(nv[q].x, nv[q].y);
                hu[2 * q + 1] = cvt2(nv[q].z, nv[q].w);
            }
            *(uint4*)&sXh[b ^ 1][xsb]     = make_uint4(hu[0], hu[1], hu[2], hu[3]);
            *(uint4*)&sXh[b ^ 1][xsb + 4] = make_uint4(hu[4], hu[5], hu[6], hu[7]);
        }
        __syncthreads();
    }

    // ---- epilogue: bias + store ----
#pragma unroll
    for (int m = 0; m < 2; m++) {
        const int r0 = wr + m * 16 + qr;
#pragma unroll
        for (int n = 0; n < 8; n++) {
            const int c0 = px0 + wc + n * 8 + qc * 2;
            *(float2*)(Zb + (size_t)r0 * NPIX + c0) =
                make_float2(acc[m][n][0] + bias[m][0], acc[m][n][1] + bias[m][0]);
            *(float2*)(Zb + (size_t)(r0 + 8) * NPIX + c0) =
                make_float2(acc[m][n][2] + bias[m][1], acc[m][n][3] + bias[m][1]);
        }
    }
}

// =====================================================================
extern "C" void kernel_launch(void* const* d_in, const int* in_sizes, int n_in,
                              void* d_out, int out_size)
{
    (void)in_sizes; (void)n_in; (void)out_size;
    const float* x        = (const float*)d_in[0];
    const float* theta_w  = (const float*)d_in[1];
    const float* theta_b  = (const float*)d_in[2];
    const float* phi_w    = (const float*)d_in[3];
    const float* phi_b    = (const float*)d_in[4];
    const float* g_w      = (const float*)d_in[5];
    const float* g_b      = (const float*)d_in[6];
    const float* W_w      = (const float*)d_in[7];
    const float* W_b      = (const float*)d_in[8];
    const float* bn_gamma = (const float*)d_in[9];
    const float* bn_beta  = (const float*)d_in[10];
    const float* bn_mean  = (const float*)d_in[11];
    const float* bn_var   = (const float*)d_in[12];
    float* out = (float*)d_out;

    cudaFuncSetAttribute(chain_kernel,
                         cudaFuncAttributeMaxDynamicSharedMemorySize, CH_SMEM);
    cudaFuncSetAttribute(apply_kernel,
                         cudaFuncAttributeMaxDynamicSharedMemorySize, AP_SMEM);

    gram_kernel<<<dim3(KSPLIT, NB), 256>>>(x);
    chain_kernel<<<NB, 256, CH_SMEM>>>(theta_w, theta_b, phi_w, phi_b,
                                       g_w, g_b, W_w, W_b,
                                       bn_gamma, bn_beta, bn_mean, bn_var);
    apply_kernel<<<dim3(NPIX / 128, NB), 256, AP_SMEM>>>(x, out);
}

// round 17
// speedup vs baseline: 1.4593x; 1.0180x over previous
#include <cuda_runtime.h>
#include <cuda_fp16.h>
#include <cstdint>
#include <math.h>

// Problem constants:
//  x: [16, 512, 64, 64] fp32 == [64 batches][128 ch][4096 px] contiguous
#define NB     64
#define CI     128
#define NPIX   4096
#define KSPLIT 8                 // gram K-split CTAs per batch (K=512 each)
#define GP2    20                // gram pair stride (16 pairs + 4) [80B, ldsm-cf]
#define APR    68                // packed pair stride (64 pairs + 4) [272B, ldsm-cf]
#define F32S   132               // chain fp32 scratch stride

// ---------------- fp16 helpers ----------------
__device__ __forceinline__ void split2(float a, float b, unsigned& hu, unsigned& lu) {
    __half2 h2 = __float22half2_rn(make_float2(a, b));
    float2 hf = __half22float2(h2);
    __half2 l2 = __float22half2_rn(make_float2(a - hf.x, b - hf.y));
    hu = *(unsigned*)&h2;
    lu = *(unsigned*)&l2;
}
__device__ __forceinline__ void split2s2(float a, float b, unsigned& hu, unsigned& lu) {
    __half2 h2 = __float22half2_rn(make_float2(a, b));
    float2 hf = __half22float2(h2);
    __half2 l2 = __float22half2_rn(make_float2((a - hf.x) * 2.0f, (b - hf.y) * 2.0f));
    hu = *(unsigned*)&h2;
    lu = *(unsigned*)&l2;
}
__device__ __forceinline__ unsigned cvt2(float a, float b) {
    __half2 h2 = __float22half2_rn(make_float2(a, b));
    return *(unsigned*)&h2;
}

// D += A(16x16,row,f16) * B(16x8,col,f16)  fp32-accum
__device__ __forceinline__ void mmah(float* d, const unsigned* a, const unsigned* b) {
    asm volatile(
        "mma.sync.aligned.m16n8k16.row.col.f32.f16.f16.f32 "
        "{%0,%1,%2,%3}, {%4,%5,%6,%7}, {%8,%9}, {%0,%1,%2,%3};"
        : "+f"(d[0]), "+f"(d[1]), "+f"(d[2]), "+f"(d[3])
        : "r"(a[0]), "r"(a[1]), "r"(a[2]), "r"(a[3]), "r"(b[0]), "r"(b[1]));
}

__device__ __forceinline__ uint32_t s2u(const void* p) {
    return (uint32_t)__cvta_generic_to_shared(p);
}
#define LDSM_X4(r, addr) \
    asm volatile("ldmatrix.sync.aligned.m8n8.x4.shared.b16 {%0,%1,%2,%3}, [%4];" \
        : "=r"((r)[0]), "=r"((r)[1]), "=r"((r)[2]), "=r"((r)[3]) : "r"(addr))
#define LDSM_X4T(r, addr) \
    asm volatile("ldmatrix.sync.aligned.m8n8.x4.trans.shared.b16 {%0,%1,%2,%3}, [%4];" \
        : "=r"((r)[0]), "=r"((r)[1]), "=r"((r)[2]), "=r"((r)[3]) : "r"(addr))

// ---------------- scratch ----------------
__device__ float    g_Gpart[NB * KSPLIT * CI * CI]; // partial E (G = (E+E^T)/2)
__device__ float    g_spart[NB * KSPLIT * CI];      // partial row sums
__device__ unsigned g_Ah2[NB * CI * 64];            // A'' fp16-hi, half2 pairs
__device__ unsigned g_Al2[NB * CI * 64];            // A'' fp16-lo, half2 pairs
__device__ float    g_bvec[NB * CI];                // folded bias b'

// =====================================================================
// Kernel 1 (round-14/15 proven, 65.7us): partial E = H H^T + H (2L)^T.
// 32-px chunks, grid (KSPLIT, NB), 256 threads, 2 CTAs/SM.
// =====================================================================
__global__ void __launch_bounds__(256, 2)
gram_kernel(const float* __restrict__ X)
{
    __shared__ unsigned sH[2][128 * GP2];
    __shared__ unsigned sL[2][128 * GP2];
    __shared__ float sred[256];

    const int t = threadIdx.x;
    const int lane = t & 31, w = t >> 5;
    const int wr = (w >> 2) * 64, wc = (w & 3) * 32;
    const int qr = lane >> 2, qc = lane & 3;
    const int kc = blockIdx.x, bb = blockIdx.y;

    const float* Xb = X + (size_t)bb * CI * NPIX + (size_t)kc * 512;
    const int lrow = t >> 1;
    const int sbase = lrow * GP2 + (t & 1) * 8;
    const float* Xr = Xb + (size_t)lrow * NPIX + (t & 1) * 16;

    const uint32_t aH[2] = {s2u(sH[0]), s2u(sH[1])};
    const uint32_t aL[2] = {s2u(sL[0]), s2u(sL[1])};

    uint32_t aoffA[4], boffB[2];
#pragma unroll
    for (int m = 0; m < 4; m++)
        aoffA[m] = (uint32_t)((wr + m * 16 + (lane & 15)) * GP2) * 4u
                 + (uint32_t)((lane >> 4) & 1) * 16u;
#pragma unroll
    for (int j = 0; j < 2; j++)
        boffB[j] = (uint32_t)((wc + j * 16 + (lane & 7) + ((lane >> 4) & 1) * 8) * GP2) * 4u
                 + (uint32_t)((lane >> 3) & 1) * 16u;

    float acc[4][4][4];
#pragma unroll
    for (int m = 0; m < 4; m++)
#pragma unroll
        for (int n = 0; n < 4; n++)
#pragma unroll
            for (int r = 0; r < 4; r++) acc[m][n][r] = 0.f;
    float mysum = 0.f;

    {
        float4 v[4];
#pragma unroll
        for (int q = 0; q < 4; q++) v[q] = *(const float4*)(Xr + 4 * q);
        unsigned hu[8], lu[8];
#pragma unroll
        for (int q = 0; q < 4; q++) {
            split2s2(v[q].x, v[q].y, hu[2 * q], lu[2 * q]);
            split2s2(v[q].z, v[q].w, hu[2 * q + 1], lu[2 * q + 1]);
            mysum += v[q].x + v[q].y + v[q].z + v[q].w;
        }
        *(uint4*)&sH[0][sbase]     = make_uint4(hu[0], hu[1], hu[2], hu[3]);
        *(uint4*)&sH[0][sbase + 4] = make_uint4(hu[4], hu[5], hu[6], hu[7]);
        *(uint4*)&sL[0][sbase]     = make_uint4(lu[0], lu[1], lu[2], lu[3]);
        *(uint4*)&sL[0][sbase + 4] = make_uint4(lu[4], lu[5], lu[6], lu[7]);
    }
    __syncthreads();

    for (int ch = 0; ch < 16; ch++) {
        const int b = ch & 1;
        float4 nv[4];
        if (ch < 15) {
#pragma unroll
            for (int q = 0; q < 4; q++)
                nv[q] = *(const float4*)(Xr + (ch + 1) * 32 + 4 * q);
        }

#pragma unroll
        for (int ks = 0; ks < 2; ks++) {
            const uint32_t kOff = (uint32_t)ks * 32u;
            unsigned Af[4][4];
#pragma unroll
            for (int m = 0; m < 4; m++) LDSM_X4(Af[m], aH[b] + aoffA[m] + kOff);
#pragma unroll
            for (int j = 0; j < 2; j++) {
                unsigned BH[4], BL[4];
                LDSM_X4(BH, aH[b] + boffB[j] + kOff);
                LDSM_X4(BL, aL[b] + boffB[j] + kOff);
                unsigned B0h[2] = {BH[0], BH[1]}, B1h[2] = {BH[2], BH[3]};
                unsigned B0l[2] = {BL[0], BL[1]}, B1l[2] = {BL[2], BL[3]};
#pragma unroll
                for (int m = 0; m < 4; m++) {
                    mmah(acc[m][2 * j],     Af[m], B0h);
                    mmah(acc[m][2 * j],     Af[m], B0l);
                    mmah(acc[m][2 * j + 1], Af[m], B1h);
                    mmah(acc[m][2 * j + 1], Af[m], B1l);
                }
            }
        }

        if (ch < 15) {
            unsigned hu[8], lu[8];
#pragma unroll
            for (int q = 0; q < 4; q++) {
                split2s2(nv[q].x, nv[q].y, hu[2 * q], lu[2 * q]);
                split2s2(nv[q].z, nv[q].w, hu[2 * q + 1], lu[2 * q + 1]);
                mysum += nv[q].x + nv[q].y + nv[q].z + nv[q].w;
            }
            *(uint4*)&sH[b ^ 1][sbase]     = make_uint4(hu[0], hu[1], hu[2], hu[3]);
            *(uint4*)&sH[b ^ 1][sbase + 4] = make_uint4(hu[4], hu[5], hu[6], hu[7]);
            *(uint4*)&sL[b ^ 1][sbase]     = make_uint4(lu[0], lu[1], lu[2], lu[3]);
            *(uint4*)&sL[b ^ 1][sbase + 4] = make_uint4(lu[4], lu[5], lu[6], lu[7]);
        }
        __syncthreads();
    }

    sred[t] = mysum;
    __syncthreads();
    if (t < 128)
        g_spart[(bb * KSPLIT + kc) * CI + t] = sred[2 * t] + sred[2 * t + 1];

    float* P = g_Gpart + ((size_t)(bb * KSPLIT + kc)) * CI * CI;
#pragma unroll
    for (int m = 0; m < 4; m++) {
        const int r0 = wr + m * 16 + qr;
#pragma unroll
        for (int n = 0; n < 4; n++) {
            const int c0 = wc + n * 8 + qc * 2;
            *(float2*)(P + (size_t)r0 * CI + c0)       = make_float2(acc[m][n][0], acc[m][n][1]);
            *(float2*)(P + (size_t)(r0 + 8) * CI + c0) = make_float2(acc[m][n][2], acc[m][n][3]);
        }
    }
}

// =====================================================================
// Kernel 2: chain, tensorized, with packed-epilogue GEMMs.
// =====================================================================
#define CH_PK   (128 * APR * 4)
#define CH_OF32 (4 * CH_PK)
#define CH_SMEM (CH_OF32 + 128 * F32S * 4)

// 3-product GEMM -> fp32 smem output (for softmax stage)
__device__ __forceinline__ void mgh3(const unsigned* __restrict__ Ah,
                                     const unsigned* __restrict__ Al,
                                     const unsigned* __restrict__ Bh,
                                     const unsigned* __restrict__ Bl,
                                     float* __restrict__ O, int t)
{
    const int lane = t & 31, w = t >> 5;
    const int wr = (w >> 2) * 64, wc = (w & 3) * 32;
    const int qr = lane >> 2, qc = lane & 3;
    float acc[4][4][4];
#pragma unroll
    for (int m = 0; m < 4; m++)
#pragma unroll
        for (int n = 0; n < 4; n++)
#pragma unroll
            for (int r = 0; r < 4; r++) acc[m][n][r] = 0.f;

#pragma unroll
    for (int s = 0; s < 8; s++) {
        const int kp = s * 8;
        unsigned Afh[4][4], Afl[4][4];
#pragma unroll
        for (int m = 0; m < 4; m++) {
            const int ar = wr + m * 16 + qr;
            Afh[m][0] = Ah[ar * APR + kp + qc];
            Afh[m][1] = Ah[(ar + 8) * APR + kp + qc];
            Afh[m][2] = Ah[ar * APR + kp + qc + 4];
            Afh[m][3] = Ah[(ar + 8) * APR + kp + qc + 4];
            Afl[m][0] = Al[ar * APR + kp + qc];
            Afl[m][1] = Al[(ar + 8) * APR + kp + qc];
            Afl[m][2] = Al[ar * APR + kp + qc + 4];
            Afl[m][3] = Al[(ar + 8) * APR + kp + qc + 4];
        }
#pragma unroll
        for (int n = 0; n < 4; n++) {
            const int br = wc + n * 8 + qr;
            unsigned Bfh[2] = {Bh[br * APR + kp + qc], Bh[br * APR + kp + qc + 4]};
            unsigned Bfl[2] = {Bl[br * APR + kp + qc], Bl[br * APR + kp + qc + 4]};
#pragma unroll
            for (int m = 0; m < 4; m++) {
                mmah(acc[m][n], Afh[m], Bfh);
                mmah(acc[m][n], Afh[m], Bfl);
                mmah(acc[m][n], Afl[m], Bfh);
            }
        }
    }
#pragma unroll
    for (int m = 0; m < 4; m++) {
        const int r0 = wr + m * 16 + qr;
#pragma unroll
        for (int n = 0; n < 4; n++) {
            const int c0 = wc + n * 8 + qc * 2;
            *(float2*)&O[r0 * F32S + c0]       = make_float2(acc[m][n][0], acc[m][n][1]);
            *(float2*)&O[(r0 + 8) * F32S + c0] = make_float2(acc[m][n][2], acc[m][n][3]);
        }
    }
}

// 3-product GEMM -> packed fp16 hi/lo output DIRECTLY (fused pack).
// Internal barrier makes it safe for (Ph,Pl) to alias an operand buffer.
__device__ __forceinline__ void mgh3_pack(const unsigned* __restrict__ Ah,
                                          const unsigned* __restrict__ Al,
                                          const unsigned* __restrict__ Bh,
                                          const unsigned* __restrict__ Bl,
                                          unsigned* __restrict__ Ph,
                                          unsigned* __restrict__ Pl, int t)
{
    const int lane = t & 31, w = t >> 5;
    const int wr = (w >> 2) * 64, wc = (w & 3) * 32;
    const int qr = lane >> 2, qc = lane & 3;
    float acc[4][4][4];
#pragma unroll
    for (int m = 0; m < 4; m++)
#pragma unroll
        for (int n = 0; n < 4; n++)
#pragma unroll
            for (int r = 0; r < 4; r++) acc[m][n][r] = 0.f;

#pragma unroll
    for (int s = 0; s < 8; s++) {
        const int kp = s * 8;
        unsigned Afh[4][4], Afl[4][4];
#pragma unroll
        for (int m = 0; m < 4; m++) {
            const int ar = wr + m * 16 + qr;
            Afh[m][0] = Ah[ar * APR + kp + qc];
            Afh[m][1] = Ah[(ar + 8) * APR + kp + qc];
            Afh[m][2] = Ah[ar * APR + kp + qc + 4];
            Afh[m][3] = Ah[(ar + 8) * APR + kp + qc + 4];
            Afl[m][0] = Al[ar * APR + kp + qc];
            Afl[m][1] = Al[(ar + 8) * APR + kp + qc];
            Afl[m][2] = Al[ar * APR + kp + qc + 4];
            Afl[m][3] = Al[(ar + 8) * APR + kp + qc + 4];
        }
#pragma unroll
        for (int n = 0; n < 4; n++) {
            const int br = wc + n * 8 + qr;
            unsigned Bfh[2] = {Bh[br * APR + kp + qc], Bh[br * APR + kp + qc + 4]};
            unsigned Bfl[2] = {Bl[br * APR + kp + qc], Bl[br * APR + kp + qc + 4]};
#pragma unroll
            for (int m = 0; m < 4; m++) {
                mmah(acc[m][n], Afh[m], Bfh);
                mmah(acc[m][n], Afh[m], Bfl);
                mmah(acc[m][n], Afl[m], Bfh);
            }
        }
    }
    __syncthreads();   // all operand reads done -> safe to overwrite in place
#pragma unroll
    for (int m = 0; m < 4; m++) {
        const int r0 = wr + m * 16 + qr;
#pragma unroll
        for (int n = 0; n < 4; n++) {
            const int p0 = (wc + n * 8) / 2 + qc;   // pair index c0/2
            unsigned hu, lu;
            split2(acc[m][n][0], acc[m][n][1], hu, lu);
            Ph[r0 * APR + p0] = hu;
            Pl[r0 * APR + p0] = lu;
            split2(acc[m][n][2], acc[m][n][3], hu, lu);
            Ph[(r0 + 8) * APR + p0] = hu;
            Pl[(r0 + 8) * APR + p0] = lu;
        }
    }
}

__device__ __forceinline__ void mgh3_final(const unsigned* __restrict__ Ah,
                                           const unsigned* __restrict__ Al,
                                           const unsigned* __restrict__ Bh,
                                           const unsigned* __restrict__ Bl,
                                           unsigned* __restrict__ gAh,
                                           unsigned* __restrict__ gAl,
                                           const float* __restrict__ scale, int t)
{
    const int lane = t & 31, w = t >> 5;
    const int wr = (w >> 2) * 64, wc = (w & 3) * 32;
    const int qr = lane >> 2, qc = lane & 3;
    float acc[4][4][4];
#pragma unroll
    for (int m = 0; m < 4; m++)
#pragma unroll
        for (int n = 0; n < 4; n++)
#pragma unroll
            for (int r = 0; r < 4; r++) acc[m][n][r] = 0.f;

#pragma unroll
    for (int s = 0; s < 8; s++) {
        const int kp = s * 8;
        unsigned Afh[4][4], Afl[4][4];
#pragma unroll
        for (int m = 0; m < 4; m++) {
            const int ar = wr + m * 16 + qr;
            Afh[m][0] = Ah[ar * APR + kp + qc];
            Afh[m][1] = Ah[(ar + 8) * APR + kp + qc];
            Afh[m][2] = Ah[ar * APR + kp + qc + 4];
            Afh[m][3] = Ah[(ar + 8) * APR + kp + qc + 4];
            Afl[m][0] = Al[ar * APR + kp + qc];
            Afl[m][1] = Al[(ar + 8) * APR + kp + qc];
            Afl[m][2] = Al[ar * APR + kp + qc + 4];
            Afl[m][3] = Al[(ar + 8) * APR + kp + qc + 4];
        }
#pragma unroll
        for (int n = 0; n < 4; n++) {
            const int br = wc + n * 8 + qr;
            unsigned Bfh[2] = {Bh[br * APR + kp + qc], Bh[br * APR + kp + qc + 4]};
            unsigned Bfl[2] = {Bl[br * APR + kp + qc], Bl[br * APR + kp + qc + 4]};
#pragma unroll
            for (int m = 0; m < 4; m++) {
                mmah(acc[m][n], Afh[m], Bfh);
                mmah(acc[m][n], Afh[m], Bfl);
                mmah(acc[m][n], Afl[m], Bfh);
            }
        }
    }
#pragma unroll
    for (int m = 0; m < 4; m++) {
        const int r0 = wr + m * 16 + qr;
        const float s0 = scale[r0], s1 = scale[r0 + 8];
#pragma unroll
        for (int n = 0; n < 4; n++) {
            const int c0 = wc + n * 8 + qc * 2;
            float v0 = s0 * acc[m][n][0] + ((r0 == c0) ? 1.f : 0.f);
            float v1 = s0 * acc[m][n][1] + ((r0 == c0 + 1) ? 1.f : 0.f);
            float v2 = s1 * acc[m][n][2] + ((r0 + 8 == c0) ? 1.f : 0.f);
            float v3 = s1 * acc[m][n][3] + ((r0 + 8 == c0 + 1) ? 1.f : 0.f);
            unsigned hu, lu;
            split2(v0, v1, hu, lu);
            gAh[r0 * 64 + c0 / 2] = hu;
            gAl[r0 * 64 + c0 / 2] = lu;
            split2(v2, v3, hu, lu);
            gAh[(r0 + 8) * 64 + c0 / 2] = hu;
            gAl[(r0 + 8) * 64 + c0 / 2] = lu;
        }
    }
}

__device__ __forceinline__ void stage_pack_gmem(const float* __restrict__ src,
                                                unsigned* __restrict__ Ph,
                                                unsigned* __restrict__ Pl, int t)
{
    const int row = t >> 1, seg = (t & 1) * 64;
    const int base = row * APR + seg / 2;
    const float4* s4 = (const float4*)(src + row * CI + seg);
#pragma unroll
    for (int j = 0; j < 16; j++) {
        float4 v = s4[j];
        unsigned h0, l0, h1, l1;
        split2(v.x, v.y, h0, l0);
        split2(v.z, v.w, h1, l1);
        *(uint2*)&Ph[base + 2 * j] = make_uint2(h0, h1);
        *(uint2*)&Pl[base + 2 * j] = make_uint2(l0, l1);
    }
}

__device__ __forceinline__ void pack_from_smem(const float* __restrict__ F,
                                               unsigned* __restrict__ Ph,
                                               unsigned* __restrict__ Pl, int t)
{
    const int row = t >> 1, seg = (t & 1) * 64;
    const int base = row * APR + seg / 2;
    const float* fr = F + row * F32S + seg;
#pragma unroll
    for (int j = 0; j < 32; j++) {
        float2 v = *(const float2*)(fr + 2 * j);
        unsigned h, l;
        split2(v.x, v.y, h, l);
        Ph[base + j] = h;
        Pl[base + j] = l;
    }
}

__device__ __forceinline__ float dot_packed(const unsigned* __restrict__ Ph,
                                            const unsigned* __restrict__ Pl,
                                            int row, const float* __restrict__ s)
{
    float acc = 0.f;
#pragma unroll 8
    for (int p = 0; p < 64; p++) {
        float2 hf = __half22float2(*(const __half2*)&Ph[row * APR + p]);
        float2 lf = __half22float2(*(const __half2*)&Pl[row * APR + p]);
        acc += (hf.x + lf.x) * s[2 * p] + (hf.y + lf.y) * s[2 * p + 1];
    }
    return acc;
}

__global__ void __launch_bounds__(256)
chain_kernel(const float* __restrict__ theta_w, const float* __restrict__ theta_b,
             const float* __restrict__ phi_w,   const float* __restrict__ phi_b,
             const float* __restrict__ g_w,     const float* __restrict__ g_b,
             const float* __restrict__ W_w,     const float* __restrict__ W_b,
             const float* __restrict__ bn_gamma, const float* __restrict__ bn_beta,
             const float* __restrict__ bn_mean,  const float* __restrict__ bn_var)
{
    extern __shared__ char csm[];
    unsigned* P0h = (unsigned*)(csm);
    unsigned* P0l = (unsigned*)(csm + CH_PK);
    unsigned* P1h = (unsigned*)(csm + 2 * CH_PK);
    unsigned* P1l = (unsigned*)(csm + 3 * CH_PK);
    float*    F32 = (float*)(csm + CH_OF32);

    __shared__ float sv_s[CI], sv_u[CI], sv_q[CI], sv_tb[CI],
                     sv_gb[CI], sv_c[CI], sv_scale[CI];

    const int t  = threadIdx.x;
    const int bb = blockIdx.x;

    // --- 1) reduce S -> F32; vectors; stage theta -> P1 ---
    const float* Gp = g_Gpart + (size_t)bb * KSPLIT * CI * CI;
    for (int idx = t; idx < CI * CI; idx += 256) {
        float v = 0.f;
#pragma unroll
        for (int ks = 0; ks < KSPLIT; ks++) v += Gp[ks * CI * CI + idx];
        F32[(idx >> 7) * F32S + (idx & 127)] = v;
    }
    if (t < CI) {
        float v = 0.f;
#pragma unroll
        for (int ks = 0; ks < KSPLIT; ks++) v += g_spart[(bb * KSPLIT + ks) * CI + t];
        sv_s[t]  = v;
        sv_tb[t] = theta_b[t];
        sv_gb[t] = g_b[t];
        sv_scale[t] = bn_gamma[t] * rsqrtf(bn_var[t] + 1e-5f);
    }
    stage_pack_gmem(theta_w, P1h, P1l, t);
    __syncthreads();

    // --- 2) symmetrize; sv_q ---
    for (int i = t; i < 8256; i += 256) {
        int r = (int)((sqrtf(8.0f * (float)i + 1.0f) - 1.0f) * 0.5f);
        if ((r + 1) * (r + 2) / 2 <= i) r++;
        if (r * (r + 1) / 2 > i) r--;
        int c = i - r * (r + 1) / 2;
        float a = F32[r * F32S + c], b = F32[c * F32S + r];
        float g = 0.5f * (a + b);
        F32[r * F32S + c] = g;
        F32[c * F32S + r] = g;
    }
    if (t < CI)
        sv_q[t] = dot_packed(P1h, P1l, t, sv_s) + 4096.0f * sv_tb[t];
    __syncthreads();

    // --- 3) pack G -> P0 ---
    pack_from_smem(F32, P0h, P0l, t);
    __syncthreads();

    // --- 4) GEMM1: T1t = theta x G -> packed P0 (in place, fused) ---
    mgh3_pack(P1h, P1l, P0h, P0l, P0h, P0l, t);
    // after internal barrier all reads of P1 are done -> restage phi into P1
    stage_pack_gmem(phi_w, P1h, P1l, t);
    __syncthreads();
    if (t < CI)
        sv_u[t] = dot_packed(P1h, P1l, t, sv_s);
    __syncthreads();

    // --- 5) GEMM2: L = phi x T1t -> F32 (softmax needs fp32) ---
    mgh3(P1h, P1l, P0h, P0l, F32, t);
    __syncthreads();

    // --- 6) softmax -> f packed into P1; sv_c ---
    if (t < CI) {
        const float w1 = sv_u[t];
        const float w2 = phi_b[t];
        float* rowp = F32 + t * F32S;
        float mx = -1e30f;
#pragma unroll 8
        for (int d = 0; d < 128; d++) {
            float v = rowp[d] + w1 * sv_tb[d] + w2 * sv_q[d];
            rowp[d] = v;
            mx = fmaxf(mx, v);
        }
        float ssum = 0.f;
#pragma unroll 8
        for (int d = 0; d < 128; d++) {
            float ev = expf(rowp[d] - mx);
            rowp[d] = ev;
            ssum += ev;
        }
        const float inv = 1.0f / ssum;
        float cacc = 0.f;
#pragma unroll
        for (int p = 0; p < 64; p++) {
            float f0 = rowp[2 * p] * inv;
            float f1 = rowp[2 * p + 1] * inv;
            cacc += f0 * sv_gb[2 * p] + f1 * sv_gb[2 * p + 1];
            unsigned h, l;
            split2(f0, f1, h, l);
            P1h[t * APR + p] = h;
            P1l[t * APR + p] = l;
        }
        sv_c[t] = cacc;
    }
    __syncthreads();

    // --- 7) g_w -> F32; transpose-pack gwT -> P0 ---
    for (int idx = t; idx < CI * CI; idx += 256)
        F32[(idx >> 7) * F32S + (idx & 127)] = g_w[idx];
    __syncthreads();
    {
        const int k = t >> 1, d0 = (t & 1) * 64;
        const int base = k * APR + d0 / 2;
#pragma unroll
        for (int p = 0; p < 32; p++) {
            const int d = d0 + 2 * p;
            unsigned h, l;
            split2(F32[d * F32S + k], F32[(d + 1) * F32S + k], h, l);
            P0h[base + p] = h;
            P0l[base + p] = l;
        }
    }
    __syncthreads();

    // --- 8) GEMM3: Mt = gwT x f -> packed P0 (in place, fused) ---
    mgh3_pack(P0h, P0l, P1h, P1l, P0h, P0l, t);
    // after internal barrier, P1 (f) reads done -> restage W_w into P1
    stage_pack_gmem(W_w, P1h, P1l, t);
    __syncthreads();

    // --- 9) bias; GEMM4: A'' = Ww x Mt -> gmem packed ---
    if (t < CI) {
        float b0 = dot_packed(P1h, P1l, t, sv_c);
        float sc = sv_scale[t];
        g_bvec[bb * CI + t] = sc * (b0 + W_b[t]) + bn_beta[t] - bn_mean[t] * sc;
    }
    mgh3_final(P1h, P1l, P0h, P0l,
               g_Ah2 + (size_t)bb * CI * 64, g_Al2 + (size_t)bb * CI * 64,
               sv_scale, t);
}

// =====================================================================
// Kernel 3 (round-15 proven): Z ~= Ah Xh + b'  (pure fp16).
// 256 threads, 2 CTAs/SM, grid (32, 64), CTA tile 128ch x 128px.
// =====================================================================
#define AP_SMEM ((128 * APR + 2 * 32 * APR) * 4)   // 52224 B

__global__ void __launch_bounds__(256, 2)
apply_kernel(const float* __restrict__ X, float* __restrict__ Z)
{
    extern __shared__ unsigned apsm[];
    unsigned* sAh = apsm;                        // [128][APR]
    unsigned* sXh[2] = {sAh + 128 * APR, sAh + 128 * APR + 32 * APR};

    const int t = threadIdx.x;
    const int lane = t & 31, w = t >> 5;
    const int wr = (w >> 1) * 32;
    const int wc = (w & 1) * 64;
    const int qr = lane >> 2, qc = lane & 3;
    const int bb = blockIdx.y;
    const int px0 = blockIdx.x * 128;

    const uint32_t aAh = s2u(sAh);
    const uint32_t aXh[2] = {s2u(sXh[0]), s2u(sXh[1])};

    uint32_t aoffA[2][2];
#pragma unroll
    for (int m = 0; m < 2; m++)
#pragma unroll
        for (int ks = 0; ks < 2; ks++)
            aoffA[m][ks] = (uint32_t)((wr + m * 16 + (lane & 15)) * APR + ks * 8) * 4u
                         + (uint32_t)((lane >> 4) & 1) * 16u;
    uint32_t boffB[2][4];
#pragma unroll
    for (int ks = 0; ks < 2; ks++)
#pragma unroll
        for (int j = 0; j < 4; j++)
            boffB[ks][j] = (uint32_t)((ks * 16 + (lane & 7) + ((lane >> 3) & 1) * 8) * APR) * 4u
                         + (uint32_t)(wc + j * 16 + ((lane >> 4) & 1) * 8) * 2u;

    {
        const int row = t >> 1, seg = (t & 1) * 32;
        const uint4* Ah = (const uint4*)(g_Ah2 + ((size_t)bb * CI + row) * 64 + seg);
#pragma unroll
        for (int j = 0; j < 8; j++)
            *(uint4*)&sAh[row * APR + seg + 4 * j] = Ah[j];
    }

    float bias[2][2];
#pragma unroll
    for (int m = 0; m < 2; m++) {
        bias[m][0] = g_bvec[bb * CI + wr + m * 16 + qr];
        bias[m][1] = g_bvec[bb * CI + wr + m * 16 + qr + 8];
    }

    const float* Xb = X + (size_t)bb * CI * NPIX;
    float* Zb = Z + (size_t)bb * CI * NPIX;

    const int rr = t >> 3, lpx = (t & 7) * 16;
    const int xsb = rr * APR + (t & 7) * 8;

    float acc[2][8][4];
#pragma unroll
    for (int m = 0; m < 2; m++)
#pragma unroll
        for (int n = 0; n < 8; n++)
#pragma unroll
            for (int r = 0; r < 4; r++) acc[m][n][r] = 0.f;

    {
        const float* src = Xb + (size_t)rr * NPIX + px0 + lpx;
        unsigned hu[8];
#pragma unroll
        for (int q = 0; q < 4; q++) {
            float4 v = *(const float4*)(src + 4 * q);
            hu[2 * q]     = cvt2(v.x, v.y);
            hu[2 * q + 1] = cvt2(v.z, v.w);
        }
        *(uint4*)&sXh[0][xsb]     = make_uint4(hu[0], hu[1], hu[2], hu[3]);
        *(uint4*)&sXh[0][xsb + 4] = make_uint4(hu[4], hu[5], hu[6], hu[7]);
    }
    __syncthreads();

    for (int g = 0; g < 4; g++) {
        const int b = g & 1;
        float4 nv[4];
        if (g < 3) {
            const float* src = Xb + (size_t)((g + 1) * 32 + rr) * NPIX + px0 + lpx;
#pragma unroll
            for (int q = 0; q < 4; q++) nv[q] = *(const float4*)(src + 4 * q);
        }

        const uint32_t gOff = (uint32_t)g * 64u;
#pragma unroll
        for (int ks = 0; ks < 2; ks++) {
            unsigned Ahf[2][4];
#pragma unroll
            for (int m = 0; m < 2; m++)
                LDSM_X4(Ahf[m], aAh + aoffA[m][ks] + gOff);
#pragma unroll
            for (int j = 0; j < 4; j++) {
                unsigned BH[4];
                LDSM_X4T(BH, aXh[b] + boffB[ks][j]);
                unsigned B0h[2] = {BH[0], BH[1]}, B1h[2] = {BH[2], BH[3]};
#pragma unroll
                for (int m = 0; m < 2; m++) {
                    mmah(acc[m][2 * j],     Ahf[m], B0h);
                    mmah(acc[m][2 * j + 1], Ahf[m], B1h);
                }
            }
        }

        if (g < 3) {
            unsigned hu[8];
#pragma unroll
            for (int q = 0; q < 4; q++) {
                hu[2 * q]     = cvt2(nv[q].x, nv[q].y);
                hu[2 * q + 1] = cvt2(nv[q].z, nv[q].w);
            }
            *(uint4*)&sXh[b ^ 1][xsb]     = make_uint4(hu[0], hu[1], hu[2], hu[3]);
            *(uint4*)&sXh[b ^ 1][xsb + 4] = make_uint4(hu[4], hu[5], hu[6], hu[7]);
        }
        __syncthreads();
    }

#pragma unroll
    for (int m = 0; m < 2; m++) {
        const int r0 = wr + m * 16 + qr;
#pragma unroll
        for (int n = 0; n < 8; n++) {
            const int c0 = px0 + wc + n * 8 + qc * 2;
            *(float2*)(Zb + (size_t)r0 * NPIX + c0) =
                make_float2(acc[m][n][0] + bias[m][0], acc[m][n][1] + bias[m][0]);
            *(float2*)(Zb + (size_t)(r0 + 8) * NPIX + c0) =
                make_float2(acc[m][n][2] + bias[m][1], acc[m][n][3] + bias[m][1]);
        }
    }
}

// =====================================================================
extern "C" void kernel_launch(void* const* d_in, const int* in_sizes, int n_in,
                              void* d_out, int out_size)
{
    (void)in_sizes; (void)n_in; (void)out_size;
    const float* x        = (const float*)d_in[0];
    const float* theta_w  = (const float*)d_in[1];
    const float* theta_b  = (const float*)d_in[2];
    const float* phi_w    = (const float*)d_in[3];
    const float* phi_b    = (const float*)d_in[4];
    const float* g_w      = (const float*)d_in[5];
    const float* g_b      = (const float*)d_in[6];
    const float* W_w      = (const float*)d_in[7];
    const float* W_b      = (const float*)d_in[8];
    const float* bn_gamma = (const float*)d_in[9];
    const float* bn_beta  = (const float*)d_in[10];
    const float* bn_mean  = (const float*)d_in[11];
    const float* bn_var   = (const float*)d_in[12];
    float* out = (float*)d_out;

    cudaFuncSetAttribute(chain_kernel,
                         cudaFuncAttributeMaxDynamicSharedMemorySize, CH_SMEM);
    cudaFuncSetAttribute(apply_kernel,
                         cudaFuncAttributeMaxDynamicSharedMemorySize, AP_SMEM);

    gram_kernel<<<dim3(KSPLIT, NB), 256>>>(x);
    chain_kernel<<<NB, 256, CH_SMEM>>>(theta_w, theta_b, phi_w, phi_b,
                                       g_w, g_b, W_w, W_b,
                                       bn_gamma, bn_beta, bn_mean, bn_var);
    apply_kernel<<<dim3(NPIX / 128, NB), 256, AP_SMEM>>>(x, out);
}